// round 2
// baseline (speedup 1.0000x reference)
#include <cuda_runtime.h>
#include <math.h>

#define BB   64
#define NN   1025
#define DD   384
#define GG   32
#define KKB  8
#define HH   128
#define CIN  1152
#define OUTD 384

// ---------------- scratch (device globals; no allocations) ----------------
__device__ float g_z[BB * CIN];            // [B][1152]
__device__ float g_U[DD * 128];            // Ufix [384][128]
__device__ float g_V[DD * 128];            // Vfix [384][128]
__device__ float g_nrm[KKB];               // basis Frobenius norms
__device__ float g_P[128 * 128];           // V^T Ufix
__device__ float g_T0[128 * OUTD];         // V^T W^T
__device__ float g_Wt[DD * OUTD];          // W^T (384x384)
__device__ float g_s[BB * KKB];            // 0.5*tanh(rot)/n_k
__device__ float g_g2[BB];                 // 2*rot_gate
__device__ float g_lg[BB];                 // local_gate
__device__ float g_scale[BB * OUTD];       // 1 + ss*tanh(coef@scale_basis)
__device__ float g_LU[BB * 128 * 128];
__device__ float g_Cp[BB * 128 * OUTD];    // D * S^-1 * T0
__device__ float g_Weff[BB * DD * OUTD];
__device__ float g_lm[(size_t)BB * NN * DD];

// ---------------- K1: per-(b,d) stats -> z = [cls, mean, var] ----------------
__global__ void k_stats(const float* __restrict__ x) {
    int idx = blockIdx.x * blockDim.x + threadIdx.x;   // B*D threads
    int b = idx / DD, d = idx % DD;
    const float* xb = x + (size_t)b * NN * DD + d;
    float cls = xb[0];
    float s = 0.f, s2 = 0.f;
    for (int n = 0; n < NN; n++) {
        float v = xb[(size_t)n * DD];
        s += v; s2 += v * v;
    }
    float mean = s / (float)NN;
    float var  = s2 / (float)NN - mean * mean;
    g_z[b * CIN + d]        = cls;
    g_z[b * CIN + 384 + d]  = mean;
    g_z[b * CIN + 768 + d]  = var;
}

// ---------------- K2: build Ufix / Vfix columns ----------------
__global__ void k_build_uv(const float* __restrict__ Lb, const float* __restrict__ Rb) {
    int idx = blockIdx.x * blockDim.x + threadIdx.x;   // 384*128
    int d = idx >> 7, j = idx & 127;
    int k = j >> 4, t = j & 15;
    if (t < 8) {
        g_U[d * 128 + j] = Lb[(k * DD + d) * 8 + t];
        g_V[d * 128 + j] = Rb[(k * DD + d) * 8 + t];
    } else {
        int tt = t - 8;
        g_U[d * 128 + j] = -Rb[(k * DD + d) * 8 + tt];
        g_V[d * 128 + j] =  Lb[(k * DD + d) * 8 + tt];
    }
}

// ---------------- K3: basis norms via 8x8 Grams ----------------
__global__ void k_norms(const float* __restrict__ Lb, const float* __restrict__ Rb) {
    int k = blockIdx.x;       // K blocks
    int t = threadIdx.x;      // 192 threads
    int which = t / 64, e = t % 64, i = e / 8, j = e % 8;
    __shared__ float gm[3][8][8];
    __shared__ float red[192];
    if (t < 192) {
        const float* Ap = (which == 0) ? Lb : Rb;   // ll: L,L ; rr: R,R ; rl: R,L
        const float* Bp = (which == 1) ? Rb : Lb;
        float acc = 0.f;
        for (int d = 0; d < DD; d++)
            acc += Ap[(k * DD + d) * 8 + i] * Bp[(k * DD + d) * 8 + j];
        gm[which][i][j] = acc;
    }
    __syncthreads();
    float part = 0.f;
    if (t < 64)
        part = 2.f * (gm[0][i][j] * gm[1][i][j] - gm[2][i][j] * gm[2][j][i]);
    red[t] = part;
    __syncthreads();
    if (t == 0) {
        float s = 0.f;
        for (int q = 0; q < 64; q++) s += red[q];
        g_nrm[k] = fmaxf(sqrtf(s), 1e-6f);
    }
}

// ---------------- K4: P = V^T U (128x128) ----------------
__global__ void k_P() {
    int idx = blockIdx.x * 256 + threadIdx.x;   // 16384
    int i = idx >> 7, j = idx & 127;
    float acc = 0.f;
    for (int d = 0; d < DD; d++)
        acc += g_V[d * 128 + i] * g_U[d * 128 + j];
    g_P[idx] = acc;
}

// ---------------- K5: T0 = V^T W^T (128x384), and Wt = W^T ----------------
__global__ void k_T0(const float* __restrict__ W) {
    int idx = blockIdx.x * 256 + threadIdx.x;   // 128*384
    int j = idx / OUTD, o = idx % OUTD;
    float acc = 0.f;
    for (int d = 0; d < DD; d++)
        acc += g_V[d * 128 + j] * W[o * DD + d];
    g_T0[idx] = acc;
}

__global__ void k_wt(const float* __restrict__ W) {
    int idx = blockIdx.x * 256 + threadIdx.x;   // 384*384
    int d = idx / OUTD, o = idx % OUTD;
    g_Wt[d * OUTD + o] = W[o * DD + d];
}

// ---------------- K6: controller MLP + gates + scale row ----------------
__global__ void k_ctrl(const float* __restrict__ w1, const float* __restrict__ b1,
                       const float* __restrict__ w_rot, const float* __restrict__ b_rot,
                       const float* __restrict__ w_rg, const float* __restrict__ b_rg,
                       const float* __restrict__ w_lg, const float* __restrict__ b_lg,
                       const float* __restrict__ w_sc, const float* __restrict__ b_sc,
                       const float* __restrict__ scale_basis,
                       const float* __restrict__ ss_ptr) {
    int b = blockIdx.x;
    int t = threadIdx.x;   // 128
    __shared__ float zs[CIN];
    __shared__ float hs[HH];
    __shared__ float coef[KKB];
    for (int c = t; c < CIN; c += 128) zs[c] = g_z[b * CIN + c];
    __syncthreads();
    {
        float acc = b1[t];
        const float* w = w1 + (size_t)t * CIN;
        for (int c = 0; c < CIN; c++) acc += zs[c] * w[c];
        float xg = acc;
        float x3 = xg * xg * xg;
        hs[t] = 0.5f * xg * (1.f + tanhf(0.7978845608028654f * (xg + 0.044715f * x3)));
    }
    __syncthreads();
    if (t < 8) {
        float acc = b_rot[t];
        for (int c = 0; c < HH; c++) acc += hs[c] * w_rot[t * HH + c];
        g_s[b * 8 + t] = 0.5f * tanhf(acc) / g_nrm[t];
    } else if (t == 8) {
        float acc = b_rg[0];
        for (int c = 0; c < HH; c++) acc += hs[c] * w_rg[c];
        g_g2[b] = 2.f / (1.f + expf(-acc));
    } else if (t == 9) {
        float acc = b_lg[0];
        for (int c = 0; c < HH; c++) acc += hs[c] * w_lg[c];
        g_lg[b] = 1.f / (1.f + expf(-acc));
    } else if (t >= 16 && t < 24) {
        int k = t - 16;
        float acc = b_sc[k];
        for (int c = 0; c < HH; c++) acc += hs[c] * w_sc[k * HH + c];
        coef[k] = tanhf(acc);
    }
    __syncthreads();
    float ss = ss_ptr[0];
    for (int o = t; o < OUTD; o += 128) {
        float acc = 0.f;
        for (int k = 0; k < KKB; k++) acc += coef[k] * scale_basis[k * OUTD + o];
        g_scale[b * OUTD + o] = 1.f + ss * tanhf(acc);
    }
}

// ---------------- K7: per-batch LU of S = I - P*D_b (no pivoting) ----------------
__global__ void k_lu() {
    int b = blockIdx.x;
    int i = threadIdx.x;       // 128 = row owner
    __shared__ float piv[128];
    __shared__ float sb[8];
    if (i < 8) sb[i] = g_s[b * 8 + i];
    __syncthreads();
    float a[128];
    #pragma unroll 8
    for (int q = 0; q < 128; q++)
        a[q] = (i == q ? 1.f : 0.f) - g_P[i * 128 + q] * sb[q >> 4];
    for (int p = 0; p < 128; p++) {
        if (i == p)
            for (int q = p; q < 128; q++) piv[q] = a[q];
        __syncthreads();
        if (i > p) {
            float l = a[p] / piv[p];
            a[p] = l;
            for (int q = p + 1; q < 128; q++) a[q] -= l * piv[q];
        }
        __syncthreads();
    }
    float* lu = g_LU + (size_t)b * 128 * 128 + i * 128;
    for (int q = 0; q < 128; q++) lu[q] = a[q];
}

// ---------------- K8: solve S X = T0, write Cp = D_b X ----------------
__global__ void k_solve() {
    int b = blockIdx.x;
    int o = threadIdx.x;       // 384 = one RHS column each
    const float* LU = g_LU + (size_t)b * 128 * 128;
    __shared__ float sb[8];
    if (o < 8) sb[o] = g_s[b * 8 + o];
    __syncthreads();
    float y[128];
    for (int p = 0; p < 128; p++) {
        float acc = g_T0[p * OUTD + o];
        const float* row = LU + p * 128;
        for (int q = 0; q < p; q++) acc -= __ldg(row + q) * y[q];
        y[p] = acc;
    }
    for (int p = 127; p >= 0; p--) {
        float acc = y[p];
        const float* row = LU + p * 128;
        for (int q = p + 1; q < 128; q++) acc -= __ldg(row + q) * y[q];
        y[p] = acc / __ldg(row + p);
    }
    float* cp = g_Cp + (size_t)b * 128 * OUTD;
    for (int j = 0; j < 128; j++) cp[j * OUTD + o] = sb[j >> 4] * y[j];
}

// ---------------- K9: W_eff_b = W^T + g2_b * Ufix @ Cp_b  (384x384, K=128) ----------------
__global__ void __launch_bounds__(256) k_weff() {
    int b  = blockIdx.z;
    int m0 = blockIdx.y * 128;   // d-tile (3)
    int n0 = blockIdx.x * 128;   // o-tile (3)
    const float* Bm = g_Cp + (size_t)b * 128 * OUTD;
    __shared__ float As[16][132];
    __shared__ float Bs[16][128];
    int tid = threadIdx.x;
    int tx = tid & 15, ty = tid >> 4;
    float acc[8][8] = {};
    int ar = tid >> 2, ac = (tid & 3) * 4;
    for (int k0 = 0; k0 < 128; k0 += 16) {
        #pragma unroll
        for (int h = 0; h < 2; h++) {
            int m = m0 + ar + h * 64;
            float4 v = *(const float4*)(g_U + (size_t)m * 128 + k0 + ac);
            As[ac + 0][ar + h * 64] = v.x;
            As[ac + 1][ar + h * 64] = v.y;
            As[ac + 2][ar + h * 64] = v.z;
            As[ac + 3][ar + h * 64] = v.w;
        }
        #pragma unroll
        for (int i2 = 0; i2 < 2; i2++) {
            int idx = tid + i2 * 256;
            int r = idx >> 5, c = (idx & 31) * 4;
            *(float4*)&Bs[r][c] = *(const float4*)(Bm + (size_t)(k0 + r) * OUTD + n0 + c);
        }
        __syncthreads();
        #pragma unroll
        for (int kk = 0; kk < 16; kk++) {
            float av[8], bv[8];
            *(float4*)&av[0] = *(const float4*)&As[kk][ty * 8];
            *(float4*)&av[4] = *(const float4*)&As[kk][ty * 8 + 4];
            *(float4*)&bv[0] = *(const float4*)&Bs[kk][tx * 8];
            *(float4*)&bv[4] = *(const float4*)&Bs[kk][tx * 8 + 4];
            #pragma unroll
            for (int i = 0; i < 8; i++)
                #pragma unroll
                for (int j = 0; j < 8; j++)
                    acc[i][j] += av[i] * bv[j];
        }
        __syncthreads();
    }
    float g = g_g2[b];
    #pragma unroll
    for (int i = 0; i < 8; i++) {
        int m = m0 + ty * 8 + i;
        float* orow = g_Weff + ((size_t)b * DD + m) * OUTD + n0 + tx * 8;
        const float* wrow = g_Wt + (size_t)m * OUTD + n0 + tx * 8;
        #pragma unroll
        for (int j = 0; j < 8; j++)
            orow[j] = wrow[j] + g * acc[i][j];
    }
}

// ---------------- K10: depthwise conv + local gate -> lm ----------------
__global__ void k_lm(const float* __restrict__ x, const float* __restrict__ ker) {
    int by = blockIdx.x;            // b*32 + y
    int b = by >> 5, y = by & 31;
    int d = threadIdx.x;            // 384
    const float* xb = x + (size_t)b * NN * DD;
    float lg = g_lg[b];
    if (y == 0) g_lm[(size_t)b * NN * DD + d] = xb[d];
    float k00 = ker[d * 9 + 0], k01 = ker[d * 9 + 1], k02 = ker[d * 9 + 2];
    float k10 = ker[d * 9 + 3], k11 = ker[d * 9 + 4], k12 = ker[d * 9 + 5];
    float k20 = ker[d * 9 + 6], k21 = ker[d * 9 + 7], k22 = ker[d * 9 + 8];
    bool up = (y > 0), dn = (y < 31);
    float ua, ub, uc;   // row y-1: cols x-1, x, x+1
    float ma, mb, mc;   // row y
    float la, lb, lc;   // row y+1
    ua = ma = la = 0.f;
    ub = up ? xb[(size_t)(1 + (y - 1) * 32) * DD + d] : 0.f;
    mb = xb[(size_t)(1 + y * 32) * DD + d];
    lb = dn ? xb[(size_t)(1 + (y + 1) * 32) * DD + d] : 0.f;
    for (int xx = 0; xx < 32; xx++) {
        if (xx < 31) {
            uc = up ? xb[(size_t)(1 + (y - 1) * 32 + xx + 1) * DD + d] : 0.f;
            mc = xb[(size_t)(1 + y * 32 + xx + 1) * DD + d];
            lc = dn ? xb[(size_t)(1 + (y + 1) * 32 + xx + 1) * DD + d] : 0.f;
        } else { uc = mc = lc = 0.f; }
        float conv = ua * k00 + ub * k01 + uc * k02
                   + ma * k10 + mb * k11 + mc * k12
                   + la * k20 + lb * k21 + lc * k22;
        float p = mb;
        g_lm[((size_t)b * NN + 1 + y * 32 + xx) * DD + d] = p + lg * (conv - p);
        ua = ub; ub = uc; ma = mb; mb = mc; la = lb; lb = lc;
    }
}

// ---------------- K11: main GEMM out = (lm @ Weff_b + bias) * scale_b ----------------
__global__ void __launch_bounds__(256) k_gemm_main(const float* __restrict__ bias,
                                                   float* __restrict__ out) {
    int b  = blockIdx.z;
    int m0 = blockIdx.y * 128;   // token tile (9)
    int n0 = blockIdx.x * 128;   // out-col tile (3)
    const float* A  = g_lm  + (size_t)b * NN * DD;
    const float* Bm = g_Weff + (size_t)b * DD * OUTD;
    __shared__ float As[16][132];
    __shared__ float Bs[16][128];
    int tid = threadIdx.x;
    int tx = tid & 15, ty = tid >> 4;
    float acc[8][8] = {};
    int ar = tid >> 2, ac = (tid & 3) * 4;
    for (int k0 = 0; k0 < DD; k0 += 16) {
        #pragma unroll
        for (int h = 0; h < 2; h++) {
            int m = m0 + ar + h * 64;
            float4 v = make_float4(0.f, 0.f, 0.f, 0.f);
            if (m < NN) v = *(const float4*)(A + (size_t)m * DD + k0 + ac);
            As[ac + 0][ar + h * 64] = v.x;
            As[ac + 1][ar + h * 64] = v.y;
            As[ac + 2][ar + h * 64] = v.z;
            As[ac + 3][ar + h * 64] = v.w;
        }
        #pragma unroll
        for (int i2 = 0; i2 < 2; i2++) {
            int idx = tid + i2 * 256;
            int r = idx >> 5, c = (idx & 31) * 4;
            *(float4*)&Bs[r][c] = *(const float4*)(Bm + (size_t)(k0 + r) * OUTD + n0 + c);
        }
        __syncthreads();
        #pragma unroll
        for (int kk = 0; kk < 16; kk++) {
            float av[8], bv[8];
            *(float4*)&av[0] = *(const float4*)&As[kk][ty * 8];
            *(float4*)&av[4] = *(const float4*)&As[kk][ty * 8 + 4];
            *(float4*)&bv[0] = *(const float4*)&Bs[kk][tx * 8];
            *(float4*)&bv[4] = *(const float4*)&Bs[kk][tx * 8 + 4];
            #pragma unroll
            for (int i = 0; i < 8; i++)
                #pragma unroll
                for (int j = 0; j < 8; j++)
                    acc[i][j] += av[i] * bv[j];
        }
        __syncthreads();
    }
    float bb[8], sc[8];
    #pragma unroll
    for (int j = 0; j < 8; j++) {
        int o = n0 + tx * 8 + j;
        bb[j] = bias[o];
        sc[j] = g_scale[b * OUTD + o];
    }
    #pragma unroll
    for (int i = 0; i < 8; i++) {
        int m = m0 + ty * 8 + i;
        if (m < NN) {
            float* orow = out + ((size_t)b * NN + m) * OUTD + n0 + tx * 8;
            #pragma unroll
            for (int j = 0; j < 8; j++)
                orow[j] = (acc[i][j] + bb[j]) * sc[j];
        }
    }
}

// ---------------- launch ----------------
extern "C" void kernel_launch(void* const* d_in, const int* in_sizes, int n_in,
                              void* d_out, int out_size) {
    const float* x      = (const float*)d_in[0];
    const float* W      = (const float*)d_in[1];
    const float* bias   = (const float*)d_in[2];
    const float* Lb     = (const float*)d_in[3];
    const float* Rb     = (const float*)d_in[4];
    const float* sbasis = (const float*)d_in[5];
    const float* ss     = (const float*)d_in[6];
    const float* dwk    = (const float*)d_in[7];
    const float* w1     = (const float*)d_in[8];
    const float* b1     = (const float*)d_in[9];
    const float* w_rot  = (const float*)d_in[10];
    const float* b_rot  = (const float*)d_in[11];
    const float* w_rg   = (const float*)d_in[12];
    const float* b_rg   = (const float*)d_in[13];
    const float* w_lg   = (const float*)d_in[14];
    const float* b_lg   = (const float*)d_in[15];
    const float* w_sc   = (const float*)d_in[16];
    const float* b_sc   = (const float*)d_in[17];
    float* out = (float*)d_out;

    k_stats<<<(BB * DD) / 128, 128>>>(x);
    k_build_uv<<<(DD * 128) / 256, 256>>>(Lb, Rb);
    k_norms<<<KKB, 192>>>(Lb, Rb);
    k_P<<<(128 * 128) / 256, 256>>>();
    k_T0<<<(128 * OUTD) / 256, 256>>>(W);
    k_wt<<<(DD * OUTD) / 256, 256>>>(W);
    k_ctrl<<<BB, 128>>>(w1, b1, w_rot, b_rot, w_rg, b_rg, w_lg, b_lg, w_sc, b_sc, sbasis, ss);
    k_lu<<<BB, 128>>>();
    k_solve<<<BB, 384>>>();
    k_lm<<<BB * 32, 384>>>(x, dwk);
    k_weff<<<dim3(3, 3, BB), 256>>>();
    k_gemm_main<<<dim3(3, 9, BB), 256>>>(bias, out);
}

// round 3
// speedup vs baseline: 1.0022x; 1.0022x over previous
#include <cuda_runtime.h>
#include <math.h>

#define BB   64
#define NN   1025
#define DD   384
#define GG   32
#define KKB  8
#define HH   128
#define CIN  1152
#define OUTD 384

// ---------------- scratch (device globals; no allocations) ----------------
__device__ float g_z[BB * CIN];            // [B][1152]
__device__ float g_U[DD * 128];            // Ufix [384][128]
__device__ float g_V[DD * 128];            // Vfix [384][128]
__device__ float g_nrm[KKB];               // basis Frobenius norms
__device__ float g_P[128 * 128];           // V^T Ufix
__device__ float g_T0[128 * OUTD];         // V^T W^T
__device__ float g_Wt[DD * OUTD];          // W^T (384x384)
__device__ float g_s[BB * KKB];            // 0.5*tanh(rot)/n_k
__device__ float g_g2[BB];                 // 2*rot_gate
__device__ float g_lg[BB];                 // local_gate
__device__ float g_scale[BB * OUTD];       // 1 + ss*tanh(coef@scale_basis)
__device__ float g_LU[BB * 128 * 128];
__device__ float g_Cp[BB * 128 * OUTD];    // D * S^-1 * T0
__device__ float g_Weff[BB * DD * OUTD];
__device__ float g_lm[(size_t)BB * NN * DD];

// ---------------- K1: per-(b,d) stats -> z = [cls, mean, var] ----------------
__global__ void k_stats(const float* __restrict__ x) {
    int idx = blockIdx.x * blockDim.x + threadIdx.x;   // B*D threads
    int b = idx / DD, d = idx % DD;
    const float* xb = x + (size_t)b * NN * DD + d;
    float cls = xb[0];
    float s = 0.f, s2 = 0.f;
    for (int n = 0; n < NN; n++) {
        float v = xb[(size_t)n * DD];
        s += v; s2 += v * v;
    }
    float mean = s / (float)NN;
    float var  = s2 / (float)NN - mean * mean;
    g_z[b * CIN + d]        = cls;
    g_z[b * CIN + 384 + d]  = mean;
    g_z[b * CIN + 768 + d]  = var;
}

// ---------------- K2: build Ufix / Vfix columns ----------------
__global__ void k_build_uv(const float* __restrict__ Lb, const float* __restrict__ Rb) {
    int idx = blockIdx.x * blockDim.x + threadIdx.x;   // 384*128
    int d = idx >> 7, j = idx & 127;
    int k = j >> 4, t = j & 15;
    if (t < 8) {
        g_U[d * 128 + j] = Lb[(k * DD + d) * 8 + t];
        g_V[d * 128 + j] = Rb[(k * DD + d) * 8 + t];
    } else {
        int tt = t - 8;
        g_U[d * 128 + j] = -Rb[(k * DD + d) * 8 + tt];
        g_V[d * 128 + j] =  Lb[(k * DD + d) * 8 + tt];
    }
}

// ---------------- K3: basis norms via 8x8 Grams ----------------
__global__ void k_norms(const float* __restrict__ Lb, const float* __restrict__ Rb) {
    int k = blockIdx.x;       // K blocks
    int t = threadIdx.x;      // 192 threads
    int which = t / 64, e = t % 64, i = e / 8, j = e % 8;
    __shared__ float gm[3][8][8];
    __shared__ float red[192];
    if (t < 192) {
        const float* Ap = (which == 0) ? Lb : Rb;   // ll: L,L ; rr: R,R ; rl: R,L
        const float* Bp = (which == 1) ? Rb : Lb;
        float acc = 0.f;
        for (int d = 0; d < DD; d++)
            acc += Ap[(k * DD + d) * 8 + i] * Bp[(k * DD + d) * 8 + j];
        gm[which][i][j] = acc;
    }
    __syncthreads();
    float part = 0.f;
    if (t < 64)
        part = 2.f * (gm[0][i][j] * gm[1][i][j] - gm[2][i][j] * gm[2][j][i]);
    red[t] = part;
    __syncthreads();
    if (t == 0) {
        float s = 0.f;
        for (int q = 0; q < 64; q++) s += red[q];
        g_nrm[k] = fmaxf(sqrtf(s), 1e-6f);
    }
}

// ---------------- K4: P = V^T U (128x128) ----------------
__global__ void k_P() {
    int idx = blockIdx.x * 256 + threadIdx.x;   // 16384
    int i = idx >> 7, j = idx & 127;
    float acc = 0.f;
    for (int d = 0; d < DD; d++)
        acc += g_V[d * 128 + i] * g_U[d * 128 + j];
    g_P[idx] = acc;
}

// ---------------- K5: T0 = V^T W^T (128x384), and Wt = W^T ----------------
__global__ void k_T0(const float* __restrict__ W) {
    int idx = blockIdx.x * 256 + threadIdx.x;   // 128*384
    int j = idx / OUTD, o = idx % OUTD;
    float acc = 0.f;
    for (int d = 0; d < DD; d++)
        acc += g_V[d * 128 + j] * W[o * DD + d];
    g_T0[idx] = acc;
}

__global__ void k_wt(const float* __restrict__ W) {
    int idx = blockIdx.x * 256 + threadIdx.x;   // 384*384
    int d = idx / OUTD, o = idx % OUTD;
    g_Wt[d * OUTD + o] = W[o * DD + d];
}

// ---------------- K6: controller MLP + gates + scale row ----------------
__global__ void k_ctrl(const float* __restrict__ w1, const float* __restrict__ b1,
                       const float* __restrict__ w_rot, const float* __restrict__ b_rot,
                       const float* __restrict__ w_rg, const float* __restrict__ b_rg,
                       const float* __restrict__ w_lg, const float* __restrict__ b_lg,
                       const float* __restrict__ w_sc, const float* __restrict__ b_sc,
                       const float* __restrict__ scale_basis,
                       const float* __restrict__ ss_ptr) {
    int b = blockIdx.x;
    int t = threadIdx.x;   // 128
    __shared__ float zs[CIN];
    __shared__ float hs[HH];
    __shared__ float coef[KKB];
    for (int c = t; c < CIN; c += 128) zs[c] = g_z[b * CIN + c];
    __syncthreads();
    {
        float acc = b1[t];
        const float* w = w1 + (size_t)t * CIN;
        for (int c = 0; c < CIN; c++) acc += zs[c] * w[c];
        float xg = acc;
        float x3 = xg * xg * xg;
        hs[t] = 0.5f * xg * (1.f + tanhf(0.7978845608028654f * (xg + 0.044715f * x3)));
    }
    __syncthreads();
    if (t < 8) {
        float acc = b_rot[t];
        for (int c = 0; c < HH; c++) acc += hs[c] * w_rot[t * HH + c];
        g_s[b * 8 + t] = 0.5f * tanhf(acc) / g_nrm[t];
    } else if (t == 8) {
        float acc = b_rg[0];
        for (int c = 0; c < HH; c++) acc += hs[c] * w_rg[c];
        g_g2[b] = 2.f / (1.f + expf(-acc));
    } else if (t == 9) {
        float acc = b_lg[0];
        for (int c = 0; c < HH; c++) acc += hs[c] * w_lg[c];
        g_lg[b] = 1.f / (1.f + expf(-acc));
    } else if (t >= 16 && t < 24) {
        int k = t - 16;
        float acc = b_sc[k];
        for (int c = 0; c < HH; c++) acc += hs[c] * w_sc[k * HH + c];
        coef[k] = tanhf(acc);
    }
    __syncthreads();
    float ss = ss_ptr[0];
    for (int o = t; o < OUTD; o += 128) {
        float acc = 0.f;
        for (int k = 0; k < KKB; k++) acc += coef[k] * scale_basis[k * OUTD + o];
        g_scale[b * OUTD + o] = 1.f + ss * tanhf(acc);
    }
}

// ---------------- K7: per-batch LU of S = I - P*D_b (no pivoting) ----------------
__global__ void k_lu() {
    int b = blockIdx.x;
    int i = threadIdx.x;       // 128 = row owner
    __shared__ float piv[128];
    __shared__ float sb[8];
    if (i < 8) sb[i] = g_s[b * 8 + i];
    __syncthreads();
    float a[128];
    #pragma unroll 8
    for (int q = 0; q < 128; q++)
        a[q] = (i == q ? 1.f : 0.f) - g_P[i * 128 + q] * sb[q >> 4];
    for (int p = 0; p < 128; p++) {
        if (i == p)
            for (int q = p; q < 128; q++) piv[q] = a[q];
        __syncthreads();
        if (i > p) {
            float l = a[p] / piv[p];
            a[p] = l;
            for (int q = p + 1; q < 128; q++) a[q] -= l * piv[q];
        }
        __syncthreads();
    }
    float* lu = g_LU + (size_t)b * 128 * 128 + i * 128;
    for (int q = 0; q < 128; q++) lu[q] = a[q];
}

// ---------------- K8: solve S X = T0, write Cp = D_b X ----------------
__global__ void k_solve() {
    int b = blockIdx.x;
    int o = threadIdx.x;       // 384 = one RHS column each
    const float* LU = g_LU + (size_t)b * 128 * 128;
    __shared__ float sb[8];
    if (o < 8) sb[o] = g_s[b * 8 + o];
    __syncthreads();
    float y[128];
    for (int p = 0; p < 128; p++) {
        float acc = g_T0[p * OUTD + o];
        const float* row = LU + p * 128;
        for (int q = 0; q < p; q++) acc -= __ldg(row + q) * y[q];
        y[p] = acc;
    }
    for (int p = 127; p >= 0; p--) {
        float acc = y[p];
        const float* row = LU + p * 128;
        for (int q = p + 1; q < 128; q++) acc -= __ldg(row + q) * y[q];
        y[p] = acc / __ldg(row + p);
    }
    float* cp = g_Cp + (size_t)b * 128 * OUTD;
    for (int j = 0; j < 128; j++) cp[j * OUTD + o] = sb[j >> 4] * y[j];
}

// ---------------- K9: W_eff_b = W^T + g2_b * Ufix @ Cp_b  (384x384, K=128) ----------------
__global__ void __launch_bounds__(256) k_weff() {
    int b  = blockIdx.z;
    int m0 = blockIdx.y * 128;   // d-tile (3)
    int n0 = blockIdx.x * 128;   // o-tile (3)
    const float* Bm = g_Cp + (size_t)b * 128 * OUTD;
    __shared__ float As[16][132];
    __shared__ float Bs[16][128];
    int tid = threadIdx.x;
    int tx = tid & 15, ty = tid >> 4;
    float acc[8][8] = {};
    int ar = tid >> 2, ac = (tid & 3) * 4;
    for (int k0 = 0; k0 < 128; k0 += 16) {
        #pragma unroll
        for (int h = 0; h < 2; h++) {
            int m = m0 + ar + h * 64;
            float4 v = *(const float4*)(g_U + (size_t)m * 128 + k0 + ac);
            As[ac + 0][ar + h * 64] = v.x;
            As[ac + 1][ar + h * 64] = v.y;
            As[ac + 2][ar + h * 64] = v.z;
            As[ac + 3][ar + h * 64] = v.w;
        }
        #pragma unroll
        for (int i2 = 0; i2 < 2; i2++) {
            int idx = tid + i2 * 256;
            int r = idx >> 5, c = (idx & 31) * 4;
            *(float4*)&Bs[r][c] = *(const float4*)(Bm + (size_t)(k0 + r) * OUTD + n0 + c);
        }
        __syncthreads();
        #pragma unroll
        for (int kk = 0; kk < 16; kk++) {
            float av[8], bv[8];
            *(float4*)&av[0] = *(const float4*)&As[kk][ty * 8];
            *(float4*)&av[4] = *(const float4*)&As[kk][ty * 8 + 4];
            *(float4*)&bv[0] = *(const float4*)&Bs[kk][tx * 8];
            *(float4*)&bv[4] = *(const float4*)&Bs[kk][tx * 8 + 4];
            #pragma unroll
            for (int i = 0; i < 8; i++)
                #pragma unroll
                for (int j = 0; j < 8; j++)
                    acc[i][j] += av[i] * bv[j];
        }
        __syncthreads();
    }
    float g = g_g2[b];
    #pragma unroll
    for (int i = 0; i < 8; i++) {
        int m = m0 + ty * 8 + i;
        float* orow = g_Weff + ((size_t)b * DD + m) * OUTD + n0 + tx * 8;
        const float* wrow = g_Wt + (size_t)m * OUTD + n0 + tx * 8;
        #pragma unroll
        for (int j = 0; j < 8; j++)
            orow[j] = wrow[j] + g * acc[i][j];
    }
}

// ---------------- K10: depthwise conv + local gate -> lm ----------------
__global__ void k_lm(const float* __restrict__ x, const float* __restrict__ ker) {
    int by = blockIdx.x;            // b*32 + y
    int b = by >> 5, y = by & 31;
    int d = threadIdx.x;            // 384
    const float* xb = x + (size_t)b * NN * DD;
    float lg = g_lg[b];
    if (y == 0) g_lm[(size_t)b * NN * DD + d] = xb[d];
    float k00 = ker[d * 9 + 0], k01 = ker[d * 9 + 1], k02 = ker[d * 9 + 2];
    float k10 = ker[d * 9 + 3], k11 = ker[d * 9 + 4], k12 = ker[d * 9 + 5];
    float k20 = ker[d * 9 + 6], k21 = ker[d * 9 + 7], k22 = ker[d * 9 + 8];
    bool up = (y > 0), dn = (y < 31);
    float ua, ub, uc;   // row y-1: cols x-1, x, x+1
    float ma, mb, mc;   // row y
    float la, lb, lc;   // row y+1
    ua = ma = la = 0.f;
    ub = up ? xb[(size_t)(1 + (y - 1) * 32) * DD + d] : 0.f;
    mb = xb[(size_t)(1 + y * 32) * DD + d];
    lb = dn ? xb[(size_t)(1 + (y + 1) * 32) * DD + d] : 0.f;
    for (int xx = 0; xx < 32; xx++) {
        if (xx < 31) {
            uc = up ? xb[(size_t)(1 + (y - 1) * 32 + xx + 1) * DD + d] : 0.f;
            mc = xb[(size_t)(1 + y * 32 + xx + 1) * DD + d];
            lc = dn ? xb[(size_t)(1 + (y + 1) * 32 + xx + 1) * DD + d] : 0.f;
        } else { uc = mc = lc = 0.f; }
        float conv = ua * k00 + ub * k01 + uc * k02
                   + ma * k10 + mb * k11 + mc * k12
                   + la * k20 + lb * k21 + lc * k22;
        float p = mb;
        g_lm[((size_t)b * NN + 1 + y * 32 + xx) * DD + d] = p + lg * (conv - p);
        ua = ub; ub = uc; ma = mb; mb = mc; la = lb; lb = lc;
    }
}

// ---------------- K11: main GEMM out = (lm @ Weff_b + bias) * scale_b ----------------
__global__ void __launch_bounds__(256) k_gemm_main(const float* __restrict__ bias,
                                                   float* __restrict__ out) {
    int b  = blockIdx.z;
    int m0 = blockIdx.y * 128;   // token tile (9)
    int n0 = blockIdx.x * 128;   // out-col tile (3)
    const float* A  = g_lm  + (size_t)b * NN * DD;
    const float* Bm = g_Weff + (size_t)b * DD * OUTD;
    __shared__ float As[16][132];
    __shared__ float Bs[16][128];
    int tid = threadIdx.x;
    int tx = tid & 15, ty = tid >> 4;
    float acc[8][8] = {};
    int ar = tid >> 2, ac = (tid & 3) * 4;
    for (int k0 = 0; k0 < DD; k0 += 16) {
        #pragma unroll
        for (int h = 0; h < 2; h++) {
            int m = m0 + ar + h * 64;
            float4 v = make_float4(0.f, 0.f, 0.f, 0.f);
            if (m < NN) v = *(const float4*)(A + (size_t)m * DD + k0 + ac);
            As[ac + 0][ar + h * 64] = v.x;
            As[ac + 1][ar + h * 64] = v.y;
            As[ac + 2][ar + h * 64] = v.z;
            As[ac + 3][ar + h * 64] = v.w;
        }
        #pragma unroll
        for (int i2 = 0; i2 < 2; i2++) {
            int idx = tid + i2 * 256;
            int r = idx >> 5, c = (idx & 31) * 4;
            *(float4*)&Bs[r][c] = *(const float4*)(Bm + (size_t)(k0 + r) * OUTD + n0 + c);
        }
        __syncthreads();
        #pragma unroll
        for (int kk = 0; kk < 16; kk++) {
            float av[8], bv[8];
            *(float4*)&av[0] = *(const float4*)&As[kk][ty * 8];
            *(float4*)&av[4] = *(const float4*)&As[kk][ty * 8 + 4];
            *(float4*)&bv[0] = *(const float4*)&Bs[kk][tx * 8];
            *(float4*)&bv[4] = *(const float4*)&Bs[kk][tx * 8 + 4];
            #pragma unroll
            for (int i = 0; i < 8; i++)
                #pragma unroll
                for (int j = 0; j < 8; j++)
                    acc[i][j] += av[i] * bv[j];
        }
        __syncthreads();
    }
    float bb[8], sc[8];
    #pragma unroll
    for (int j = 0; j < 8; j++) {
        int o = n0 + tx * 8 + j;
        bb[j] = bias[o];
        sc[j] = g_scale[b * OUTD + o];
    }
    #pragma unroll
    for (int i = 0; i < 8; i++) {
        int m = m0 + ty * 8 + i;
        if (m < NN) {
            float* orow = out + ((size_t)b * NN + m) * OUTD + n0 + tx * 8;
            #pragma unroll
            for (int j = 0; j < 8; j++)
                orow[j] = (acc[i][j] + bb[j]) * sc[j];
        }
    }
}

// ---------------- launch ----------------
extern "C" void kernel_launch(void* const* d_in, const int* in_sizes, int n_in,
                              void* d_out, int out_size) {
    const float* x      = (const float*)d_in[0];
    const float* W      = (const float*)d_in[1];
    const float* bias   = (const float*)d_in[2];
    const float* Lb     = (const float*)d_in[3];
    const float* Rb     = (const float*)d_in[4];
    const float* sbasis = (const float*)d_in[5];
    const float* ss     = (const float*)d_in[6];
    const float* dwk    = (const float*)d_in[7];
    const float* w1     = (const float*)d_in[8];
    const float* b1     = (const float*)d_in[9];
    const float* w_rot  = (const float*)d_in[10];
    const float* b_rot  = (const float*)d_in[11];
    const float* w_rg   = (const float*)d_in[12];
    const float* b_rg   = (const float*)d_in[13];
    const float* w_lg   = (const float*)d_in[14];
    const float* b_lg   = (const float*)d_in[15];
    const float* w_sc   = (const float*)d_in[16];
    const float* b_sc   = (const float*)d_in[17];
    float* out = (float*)d_out;

    k_stats<<<(BB * DD) / 128, 128>>>(x);
    k_build_uv<<<(DD * 128) / 256, 256>>>(Lb, Rb);
    k_norms<<<KKB, 192>>>(Lb, Rb);
    k_P<<<(128 * 128) / 256, 256>>>();
    k_T0<<<(128 * OUTD) / 256, 256>>>(W);
    k_wt<<<(DD * OUTD) / 256, 256>>>(W);
    k_ctrl<<<BB, 128>>>(w1, b1, w_rot, b_rot, w_rg, b_rg, w_lg, b_lg, w_sc, b_sc, sbasis, ss);
    k_lu<<<BB, 128>>>();
    k_solve<<<BB, 384>>>();
    k_lm<<<BB * 32, 384>>>(x, dwk);
    k_weff<<<dim3(3, 3, BB), 256>>>();
    k_gemm_main<<<dim3(3, 9, BB), 256>>>(bias, out);
}

// round 5
// speedup vs baseline: 1.2800x; 1.2771x over previous
#include <cuda_runtime.h>
#include <cuda_bf16.h>
#include <math.h>
#include <stdint.h>

#define BB 64
#define NN 1025
#define DD 384
#define KKB 8
#define HH 128
#define CIN 1152
#define OUTD 384

__device__ float g_z[BB * CIN];
__device__ float g_U[DD * 128];
__device__ float g_V[DD * 128];
__device__ float g_nrm[KKB];
__device__ float g_P[128 * 128];
__device__ float g_T0[128 * OUTD];
__device__ float g_s[BB * KKB];
__device__ float g_g2[BB];
__device__ float g_lg[BB];
__device__ float g_scale[BB * OUTD];
__device__ float g_LU[BB * 128 * 128];
__device__ float g_Sinv[BB * 128 * 128];
__device__ float g_E[BB * DD * 128];
__device__ __nv_bfloat16 g_WTh[(size_t)BB * OUTD * DD];
__device__ __nv_bfloat16 g_WTl[(size_t)BB * OUTD * DD];
__device__ __nv_bfloat16 g_lmh[(size_t)BB * NN * DD];
__device__ __nv_bfloat16 g_lml[(size_t)BB * NN * DD];

__device__ __forceinline__ uint32_t smem_u32(const void* p) {
    return (uint32_t)__cvta_generic_to_shared(p);
}

__global__ void k_stats(const float* __restrict__ x) {
    int idx = blockIdx.x * blockDim.x + threadIdx.x;
    int b = idx / DD, d = idx % DD;
    const float* xb = x + (size_t)b * NN * DD + d;
    float cls = xb[0], s = 0.f, s2 = 0.f;
    for (int n = 0; n < NN; n++) { float v = xb[(size_t)n * DD]; s += v; s2 += v * v; }
    float mean = s / (float)NN;
    g_z[b * CIN + d] = cls;
    g_z[b * CIN + 384 + d] = mean;
    g_z[b * CIN + 768 + d] = s2 / (float)NN - mean * mean;
}

__global__ void k_build_uv(const float* __restrict__ Lb, const float* __restrict__ Rb) {
    int idx = blockIdx.x * blockDim.x + threadIdx.x;
    int d = idx >> 7, j = idx & 127, k = j >> 4, t = j & 15;
    if (t < 8) {
        g_U[d * 128 + j] = Lb[(k * DD + d) * 8 + t];
        g_V[d * 128 + j] = Rb[(k * DD + d) * 8 + t];
    } else {
        g_U[d * 128 + j] = -Rb[(k * DD + d) * 8 + t - 8];
        g_V[d * 128 + j] =  Lb[(k * DD + d) * 8 + t - 8];
    }
}

__global__ void k_norms(const float* __restrict__ Lb, const float* __restrict__ Rb) {
    int k = blockIdx.x, t = threadIdx.x;
    int which = t / 64, e = t % 64, i = e / 8, j = e % 8;
    __shared__ float gm[3][8][8];
    __shared__ float red[192];
    if (t < 192) {
        const float* Ap = (which == 0) ? Lb : Rb;
        const float* Bp = (which == 1) ? Rb : Lb;
        float acc = 0.f;
        for (int d = 0; d < DD; d++) acc += Ap[(k * DD + d) * 8 + i] * Bp[(k * DD + d) * 8 + j];
        gm[which][i][j] = acc;
    }
    __syncthreads();
    float part = 0.f;
    if (t < 64) part = 2.f * (gm[0][i][j] * gm[1][i][j] - gm[2][i][j] * gm[2][j][i]);
    red[t] = part;
    __syncthreads();
    if (t == 0) {
        float s = 0.f;
        for (int q = 0; q < 64; q++) s += red[q];
        g_nrm[k] = fmaxf(sqrtf(s), 1e-6f);
    }
}

__global__ void k_P() {
    int idx = blockIdx.x * 256 + threadIdx.x;
    int i = idx >> 7, j = idx & 127;
    float acc = 0.f;
    for (int d = 0; d < DD; d++) acc += g_V[d * 128 + i] * g_U[d * 128 + j];
    g_P[idx] = acc;
}

__global__ void k_T0(const float* __restrict__ W) {
    int idx = blockIdx.x * 256 + threadIdx.x;
    int j = idx / OUTD, o = idx % OUTD;
    float acc = 0.f;
    for (int d = 0; d < DD; d++) acc += g_V[d * 128 + j] * W[o * DD + d];
    g_T0[idx] = acc;
}

__global__ void k_ctrl(const float* __restrict__ w1, const float* __restrict__ b1,
                       const float* __restrict__ w_rot, const float* __restrict__ b_rot,
                       const float* __restrict__ w_rg, const float* __restrict__ b_rg,
                       const float* __restrict__ w_lg, const float* __restrict__ b_lg,
                       const float* __restrict__ w_sc, const float* __restrict__ b_sc,
                       const float* __restrict__ scale_basis, const float* __restrict__ ss_ptr) {
    int b = blockIdx.x, t = threadIdx.x;
    __shared__ float zs[CIN];
    __shared__ float hs[HH];
    __shared__ float coef[KKB];
    for (int c = t; c < CIN; c += 128) zs[c] = g_z[b * CIN + c];
    __syncthreads();
    {
        float acc = b1[t];
        const float* w = w1 + (size_t)t * CIN;
        for (int c = 0; c < CIN; c++) acc += zs[c] * w[c];
        float xg = acc, x3 = xg * xg * xg;
        hs[t] = 0.5f * xg * (1.f + tanhf(0.7978845608028654f * (xg + 0.044715f * x3)));
    }
    __syncthreads();
    if (t < 8) {
        float acc = b_rot[t];
        for (int c = 0; c < HH; c++) acc += hs[c] * w_rot[t * HH + c];
        g_s[b * 8 + t] = 0.5f * tanhf(acc) / g_nrm[t];
    } else if (t == 8) {
        float acc = b_rg[0];
        for (int c = 0; c < HH; c++) acc += hs[c] * w_rg[c];
        g_g2[b] = 2.f / (1.f + expf(-acc));
    } else if (t == 9) {
        float acc = b_lg[0];
        for (int c = 0; c < HH; c++) acc += hs[c] * w_lg[c];
        g_lg[b] = 1.f / (1.f + expf(-acc));
    } else if (t >= 16 && t < 24) {
        int k = t - 16;
        float acc = b_sc[k];
        for (int c = 0; c < HH; c++) acc += hs[c] * w_sc[k * HH + c];
        coef[k] = tanhf(acc);
    }
    __syncthreads();
    float ss = ss_ptr[0];
    for (int o = t; o < OUTD; o += 128) {
        float acc = 0.f;
        for (int k = 0; k < KKB; k++) acc += coef[k] * scale_basis[k * OUTD + o];
        g_scale[b * OUTD + o] = 1.f + ss * tanhf(acc);
    }
}

__global__ void k_lu() {
    int b = blockIdx.x, i = threadIdx.x;
    __shared__ float piv[128];
    __shared__ float sb[8];
    if (i < 8) sb[i] = g_s[b * 8 + i];
    __syncthreads();
    float a[128];
    #pragma unroll 8
    for (int q = 0; q < 128; q++)
        a[q] = (i == q ? 1.f : 0.f) - g_P[i * 128 + q] * sb[q >> 4];
    for (int p = 0; p < 128; p++) {
        if (i == p) for (int q = p; q < 128; q++) piv[q] = a[q];
        __syncthreads();
        if (i > p) {
            float l = a[p] / piv[p];
            a[p] = l;
            for (int q = p + 1; q < 128; q++) a[q] -= l * piv[q];
        }
        __syncthreads();
    }
    float* lu = g_LU + (size_t)b * 128 * 128 + i * 128;
    for (int q = 0; q < 128; q++) lu[q] = a[q];
}

__global__ void k_sinv() {
    int blk = blockIdx.x, b = blk >> 1;
    int c = threadIdx.x, col = (blk & 1) * 64 + c;
    __shared__ float y[128][65];
    const float* LU = g_LU + (size_t)b * 128 * 128;
    for (int p = 0; p < 128; p++) {
        float acc = (p == col) ? 1.f : 0.f;
        const float* row = LU + p * 128;
        for (int q = 0; q < p; q++) acc -= row[q] * y[q][c];
        y[p][c] = acc;
    }
    for (int p = 127; p >= 0; p--) {
        float acc = y[p][c];
        const float* row = LU + p * 128;
        for (int q = p + 1; q < 128; q++) acc -= row[q] * y[q][c];
        y[p][c] = acc / row[p];
    }
    float* sv = g_Sinv + (size_t)b * 128 * 128;
    for (int p = 0; p < 128; p++) sv[p * 128 + col] = y[p][c];
}

// E = U * D * Sinv  (384 x 128, K=128)
__global__ void __launch_bounds__(256) k_E() {
    int b = blockIdx.z, d0 = blockIdx.y * 128;
    __shared__ __align__(16) float As[16][132];
    __shared__ __align__(16) float Bs[16][132];
    __shared__ float sb[8];
    int tid = threadIdx.x, tx = tid & 15, ty = tid >> 4;
    if (tid < 8) sb[tid] = g_s[b * 8 + tid];
    __syncthreads();
    const float* Sv = g_Sinv + (size_t)b * 128 * 128;
    float acc[8][8] = {};
    int ar = tid >> 2, ac = (tid & 3) * 4;
    for (int k0 = 0; k0 < 128; k0 += 16) {
        #pragma unroll
        for (int h = 0; h < 2; h++) {
            int d = d0 + ar + h * 64;
            float4 v = *(const float4*)(g_U + (size_t)d * 128 + k0 + ac);
            As[ac + 0][ar + h * 64] = v.x * sb[(k0 + ac + 0) >> 4];
            As[ac + 1][ar + h * 64] = v.y * sb[(k0 + ac + 1) >> 4];
            As[ac + 2][ar + h * 64] = v.z * sb[(k0 + ac + 2) >> 4];
            As[ac + 3][ar + h * 64] = v.w * sb[(k0 + ac + 3) >> 4];
        }
        #pragma unroll
        for (int i2 = 0; i2 < 2; i2++) {
            int idx = tid + i2 * 256;
            int r = idx >> 5, cc = (idx & 31) * 4;
            *(float4*)&Bs[r][cc] = *(const float4*)(Sv + (size_t)(k0 + r) * 128 + cc);
        }
        __syncthreads();
        #pragma unroll
        for (int kk = 0; kk < 16; kk++) {
            float av[8], bv[8];
            *(float4*)&av[0] = *(const float4*)&As[kk][ty * 8];
            *(float4*)&av[4] = *(const float4*)&As[kk][ty * 8 + 4];
            *(float4*)&bv[0] = *(const float4*)&Bs[kk][tx * 8];
            *(float4*)&bv[4] = *(const float4*)&Bs[kk][tx * 8 + 4];
            #pragma unroll
            for (int i = 0; i < 8; i++)
                #pragma unroll
                for (int j = 0; j < 8; j++) acc[i][j] += av[i] * bv[j];
        }
        __syncthreads();
    }
    #pragma unroll
    for (int i = 0; i < 8; i++) {
        float* erow = g_E + ((size_t)b * DD + d0 + ty * 8 + i) * 128 + tx * 8;
        *(float4*)&erow[0] = *(float4*)&acc[i][0];
        *(float4*)&erow[4] = *(float4*)&acc[i][4];
    }
}

// WeffT[b][o][d] = W[o][d] + g2*(E@T0)[d][o]  -> bf16 hi/lo, K-major
__global__ void __launch_bounds__(256) k_weffT(const float* __restrict__ W) {
    int b = blockIdx.z, o0 = blockIdx.y * 128, d0 = blockIdx.x * 128;
    __shared__ __align__(16) float As[16][132];
    __shared__ __align__(16) float Bs[16][132];
    int tid = threadIdx.x, tx = tid & 15, ty = tid >> 4;
    const float* Eb = g_E + (size_t)b * DD * 128;
    float acc[8][8] = {};
    int ar = tid >> 2, ac = (tid & 3) * 4;
    for (int k0 = 0; k0 < 128; k0 += 16) {
        #pragma unroll
        for (int i2 = 0; i2 < 2; i2++) {
            int idx = tid + i2 * 256;
            int r = idx >> 5, cc = (idx & 31) * 4;
            *(float4*)&As[r][cc] = *(const float4*)(g_T0 + (size_t)(k0 + r) * OUTD + o0 + cc);
        }
        #pragma unroll
        for (int h = 0; h < 2; h++) {
            int d = d0 + ar + h * 64;
            float4 v = *(const float4*)(Eb + (size_t)d * 128 + k0 + ac);
            Bs[ac + 0][ar + h * 64] = v.x;
            Bs[ac + 1][ar + h * 64] = v.y;
            Bs[ac + 2][ar + h * 64] = v.z;
            Bs[ac + 3][ar + h * 64] = v.w;
        }
        __syncthreads();
        #pragma unroll
        for (int kk = 0; kk < 16; kk++) {
            float av[8], bv[8];
            *(float4*)&av[0] = *(const float4*)&As[kk][ty * 8];
            *(float4*)&av[4] = *(const float4*)&As[kk][ty * 8 + 4];
            *(float4*)&bv[0] = *(const float4*)&Bs[kk][tx * 8];
            *(float4*)&bv[4] = *(const float4*)&Bs[kk][tx * 8 + 4];
            #pragma unroll
            for (int i = 0; i < 8; i++)
                #pragma unroll
                for (int j = 0; j < 8; j++) acc[i][j] += av[i] * bv[j];
        }
        __syncthreads();
    }
    float g = g_g2[b];
    #pragma unroll
    for (int i = 0; i < 8; i++) {
        int o = o0 + ty * 8 + i;
        const float* wrow = W + (size_t)o * DD + d0 + tx * 8;
        __align__(16) __nv_bfloat16 hb[8], lb[8];
        #pragma unroll
        for (int j = 0; j < 8; j++) {
            float v = wrow[j] + g * acc[i][j];
            __nv_bfloat16 h = __float2bfloat16(v);
            hb[j] = h;
            lb[j] = __float2bfloat16(v - __bfloat162float(h));
        }
        size_t off = ((size_t)b * OUTD + o) * DD + d0 + tx * 8;
        *(uint4*)(g_WTh + off) = *(uint4*)hb;
        *(uint4*)(g_WTl + off) = *(uint4*)lb;
    }
}

__global__ void k_lm(const float* __restrict__ x, const float* __restrict__ ker) {
    int by = blockIdx.x;
    int b = by >> 5, y = by & 31, d = threadIdx.x;
    const float* xb = x + (size_t)b * NN * DD;
    float lg = g_lg[b];
    if (y == 0) {
        float v = xb[d];
        __nv_bfloat16 h = __float2bfloat16(v);
        g_lmh[(size_t)b * NN * DD + d] = h;
        g_lml[(size_t)b * NN * DD + d] = __float2bfloat16(v - __bfloat162float(h));
    }
    float k00 = ker[d * 9 + 0], k01 = ker[d * 9 + 1], k02 = ker[d * 9 + 2];
    float k10 = ker[d * 9 + 3], k11 = ker[d * 9 + 4], k12 = ker[d * 9 + 5];
    float k20 = ker[d * 9 + 6], k21 = ker[d * 9 + 7], k22 = ker[d * 9 + 8];
    bool up = (y > 0), dn = (y < 31);
    float ua = 0.f, ma = 0.f, la = 0.f, ub, mb, mc, lb, uc, lc;
    ub = up ? xb[(size_t)(1 + (y - 1) * 32) * DD + d] : 0.f;
    mb = xb[(size_t)(1 + y * 32) * DD + d];
    lb = dn ? xb[(size_t)(1 + (y + 1) * 32) * DD + d] : 0.f;
    for (int xx = 0; xx < 32; xx++) {
        if (xx < 31) {
            uc = up ? xb[(size_t)(1 + (y - 1) * 32 + xx + 1) * DD + d] : 0.f;
            mc = xb[(size_t)(1 + y * 32 + xx + 1) * DD + d];
            lc = dn ? xb[(size_t)(1 + (y + 1) * 32 + xx + 1) * DD + d] : 0.f;
        } else { uc = mc = lc = 0.f; }
        float conv = ua * k00 + ub * k01 + uc * k02 + ma * k10 + mb * k11 + mc * k12
                   + la * k20 + lb * k21 + lc * k22;
        float v = mb + lg * (conv - mb);
        size_t oi = ((size_t)b * NN + 1 + y * 32 + xx) * DD + d;
        __nv_bfloat16 h = __float2bfloat16(v);
        g_lmh[oi] = h;
        g_lml[oi] = __float2bfloat16(v - __bfloat162float(h));
        ua = ub; ub = uc; ma = mb; mb = mc; la = lb; lb = lc;
    }
}

// ---------------- main GEMM via mma.sync (bf16 hi/lo, 3 segments) ----------------
// out[b,m,o] = (sum_d lm[b,m,d]*WeffT[b,o,d] + bias[o]) * scale[b,o]
#define BK 32
#define ROWB 80                 // padded row stride in bytes (32 bf16 + 8 pad)
#define TILEB (128 * ROWB)      // 10240 B per operand tile
#define NCHUNK 36               // 3 segments x 12 k-chunks

__device__ __forceinline__ void cp16(uint32_t dst, const void* src, int bytes) {
    asm volatile("cp.async.cg.shared.global [%0], [%1], 16, %2;"
                 :: "r"(dst), "l"(src), "r"(bytes) : "memory");
}

__global__ void __launch_bounds__(256, 2) k_gemm_mma(const float* __restrict__ bias,
                                                     float* __restrict__ out) {
    __shared__ __align__(16) unsigned char sm[2 * 2 * TILEB];
    __shared__ float s_bias[128], s_scale[128];
    int b = blockIdx.z, m0 = blockIdx.y * 128, n0 = blockIdx.x * 128;
    int tid = threadIdx.x, lane = tid & 31, wid = tid >> 5;
    int wm = wid & 1, wn = wid >> 1;          // 2 (m) x 4 (n) warps

    if (tid < 128) {
        s_bias[tid] = bias[n0 + tid];
        s_scale[tid] = g_scale[b * OUTD + n0 + tid];
    }

    const __nv_bfloat16* Aseg[3] = { g_lmh, g_lml, g_lmh };
    const __nv_bfloat16* Bseg[3] = { g_WTh, g_WTh, g_WTl };

    uint32_t smb = smem_u32(sm);
    float acc[4][4][4];
    #pragma unroll
    for (int i = 0; i < 4; i++)
        #pragma unroll
        for (int j = 0; j < 4; j++)
            #pragma unroll
            for (int q = 0; q < 4; q++) acc[i][j][q] = 0.f;

    // per-thread load coords: 2 x 16B per operand per chunk
    int ci0 = tid, ci1 = tid + 256;
    int r0 = ci0 >> 2, ch0 = ci0 & 3;
    int r1 = ci1 >> 2, ch1 = ci1 & 3;
    int am0 = m0 + r0, am1 = m0 + r1;
    size_t aoff0 = ((size_t)b * NN + (am0 < NN ? am0 : 0)) * DD;
    size_t aoff1 = ((size_t)b * NN + (am1 < NN ? am1 : 0)) * DD;
    size_t boff0 = ((size_t)b * OUTD + n0 + r0) * DD;
    size_t boff1 = ((size_t)b * OUTD + n0 + r1) * DD;
    int av0 = (am0 < NN) ? 16 : 0, av1 = (am1 < NN) ? 16 : 0;

    #define LOAD_CHUNK(c, s) do { \
        int seg = (c) / 12, k0 = ((c) % 12) * BK; \
        const __nv_bfloat16* Ap = Aseg[seg]; \
        const __nv_bfloat16* Bp = Bseg[seg]; \
        uint32_t Ab = smb + (uint32_t)(s) * (2 * TILEB); \
        uint32_t Bb = Ab + TILEB; \
        cp16(Ab + r0 * ROWB + ch0 * 16, Ap + aoff0 + k0 + ch0 * 8, av0); \
        cp16(Ab + r1 * ROWB + ch1 * 16, Ap + aoff1 + k0 + ch1 * 8, av1); \
        cp16(Bb + r0 * ROWB + ch0 * 16, Bp + boff0 + k0 + ch0 * 8, 16); \
        cp16(Bb + r1 * ROWB + ch1 * 16, Bp + boff1 + k0 + ch1 * 8, 16); \
    } while (0)

    LOAD_CHUNK(0, 0);
    asm volatile("cp.async.commit_group;" ::: "memory");

    for (int c = 0; c < NCHUNK; c++) {
        if (c + 1 < NCHUNK) {
            LOAD_CHUNK(c + 1, (c + 1) & 1);
            asm volatile("cp.async.commit_group;" ::: "memory");
            asm volatile("cp.async.wait_group 1;" ::: "memory");
        } else {
            asm volatile("cp.async.wait_group 0;" ::: "memory");
        }
        __syncthreads();

        uint32_t As = smb + (uint32_t)(c & 1) * (2 * TILEB);
        uint32_t Bs = As + TILEB;
        #pragma unroll
        for (int kstep = 0; kstep < 2; kstep++) {
            uint32_t a[4][4], bf[4][2];
            #pragma unroll
            for (int mf = 0; mf < 4; mf++) {
                uint32_t addr = As + (uint32_t)((wm * 64 + mf * 16 + (lane & 15)) * ROWB
                              + (kstep * 2 + (lane >> 4)) * 16);
                asm volatile("ldmatrix.sync.aligned.m8n8.x4.shared.b16 {%0,%1,%2,%3}, [%4];"
                    : "=r"(a[mf][0]), "=r"(a[mf][1]), "=r"(a[mf][2]), "=r"(a[mf][3]) : "r"(addr));
            }
            #pragma unroll
            for (int nf2 = 0; nf2 < 2; nf2++) {
                int g = lane >> 3;
                uint32_t addr = Bs + (uint32_t)((wn * 32 + nf2 * 16 + ((g >> 1) << 3) + (lane & 7)) * ROWB
                              + (kstep * 2 + (g & 1)) * 16);
                uint32_t q0, q1, q2, q3;
                asm volatile("ldmatrix.sync.aligned.m8n8.x4.shared.b16 {%0,%1,%2,%3}, [%4];"
                    : "=r"(q0), "=r"(q1), "=r"(q2), "=r"(q3) : "r"(addr));
                bf[nf2 * 2][0] = q0; bf[nf2 * 2][1] = q1;
                bf[nf2 * 2 + 1][0] = q2; bf[nf2 * 2 + 1][1] = q3;
            }
            #pragma unroll
            for (int mf = 0; mf < 4; mf++)
                #pragma unroll
                for (int nf = 0; nf < 4; nf++) {
                    asm volatile(
                        "mma.sync.aligned.m16n8k16.row.col.f32.bf16.bf16.f32 "
                        "{%0,%1,%2,%3}, {%4,%5,%6,%7}, {%8,%9}, {%0,%1,%2,%3};"
                        : "+f"(acc[mf][nf][0]), "+f"(acc[mf][nf][1]),
                          "+f"(acc[mf][nf][2]), "+f"(acc[mf][nf][3])
                        : "r"(a[mf][0]), "r"(a[mf][1]), "r"(a[mf][2]), "r"(a[mf][3]),
                          "r"(bf[nf][0]), "r"(bf[nf][1]));
                }
        }
        __syncthreads();
    }

    int gr = lane >> 2, gc = (lane & 3) * 2;
    #pragma unroll
    for (int mf = 0; mf < 4; mf++) {
        #pragma unroll
        for (int nf = 0; nf < 4; nf++) {
            int nl = wn * 32 + nf * 8 + gc;
            float b0 = s_bias[nl], b1 = s_bias[nl + 1];
            float sc0 = s_scale[nl], sc1 = s_scale[nl + 1];
            int mrow = m0 + wm * 64 + mf * 16 + gr;
            if (mrow < NN) {
                float2 v = make_float2((acc[mf][nf][0] + b0) * sc0, (acc[mf][nf][1] + b1) * sc1);
                *(float2*)(out + ((size_t)b * NN + mrow) * OUTD + n0 + nl) = v;
            }
            if (mrow + 8 < NN) {
                float2 v = make_float2((acc[mf][nf][2] + b0) * sc0, (acc[mf][nf][3] + b1) * sc1);
                *(float2*)(out + ((size_t)b * NN + mrow + 8) * OUTD + n0 + nl) = v;
            }
        }
    }
}

extern "C" void kernel_launch(void* const* d_in, const int* in_sizes, int n_in,
                              void* d_out, int out_size) {
    const float* x      = (const float*)d_in[0];
    const float* W      = (const float*)d_in[1];
    const float* bias   = (const float*)d_in[2];
    const float* Lb     = (const float*)d_in[3];
    const float* Rb     = (const float*)d_in[4];
    const float* sbasis = (const float*)d_in[5];
    const float* ss     = (const float*)d_in[6];
    const float* dwk    = (const float*)d_in[7];
    const float* w1     = (const float*)d_in[8];
    const float* b1     = (const float*)d_in[9];
    const float* w_rot  = (const float*)d_in[10];
    const float* b_rot  = (const float*)d_in[11];
    const float* w_rg   = (const float*)d_in[12];
    const float* b_rg   = (const float*)d_in[13];
    const float* w_lg   = (const float*)d_in[14];
    const float* b_lg   = (const float*)d_in[15];
    const float* w_sc   = (const float*)d_in[16];
    const float* b_sc   = (const float*)d_in[17];
    float* out = (float*)d_out;

    k_stats<<<(BB * DD) / 128, 128>>>(x);
    k_build_uv<<<(DD * 128) / 256, 256>>>(Lb, Rb);
    k_norms<<<KKB, 192>>>(Lb, Rb);
    k_P<<<(128 * 128) / 256, 256>>>();
    k_T0<<<(128 * OUTD) / 256, 256>>>(W);
    k_ctrl<<<BB, 128>>>(w1, b1, w_rot, b_rot, w_rg, b_rg, w_lg, b_lg, w_sc, b_sc, sbasis, ss);
    k_lu<<<BB, 128>>>();
    k_sinv<<<BB * 2, 64>>>();
    k_E<<<dim3(1, 3, BB), 256>>>();
    k_weffT<<<dim3(3, 3, BB), 256>>>(W);
    k_lm<<<BB * 32, 384>>>(x, dwk);
    k_gemm_mma<<<dim3(3, 9, BB), 256>>>(bias, out);
}

// round 6
// speedup vs baseline: 1.5210x; 1.1883x over previous
#include <cuda_runtime.h>
#include <cuda_bf16.h>
#include <math.h>
#include <stdint.h>

#define BB 64
#define NN 1025
#define DD 384
#define KKB 8
#define HH 128
#define CIN 1152
#define OUTD 384

__device__ float g_z[BB * CIN];
__device__ float g_U[DD * 128];
__device__ float g_V[DD * 128];
__device__ float g_nrm[KKB];
__device__ float g_P[128 * 128];
__device__ float g_T0[128 * OUTD];
__device__ float g_s[BB * KKB];
__device__ float g_g2[BB];
__device__ float g_lg[BB];
__device__ float g_scale[BB * OUTD];
__device__ float g_Sinv[BB * 128 * 128];   // D * S^-1 (pre-scaled)
__device__ float g_E[BB * DD * 128];
__device__ __nv_bfloat16 g_WTh[(size_t)BB * OUTD * DD];
__device__ __nv_bfloat16 g_WTl[(size_t)BB * OUTD * DD];
__device__ __nv_bfloat16 g_lmh[(size_t)BB * NN * DD];
__device__ __nv_bfloat16 g_lml[(size_t)BB * NN * DD];

__device__ __forceinline__ uint32_t smem_u32(const void* p) {
    return (uint32_t)__cvta_generic_to_shared(p);
}

__global__ void k_stats(const float* __restrict__ x) {
    int idx = blockIdx.x * blockDim.x + threadIdx.x;
    int b = idx / DD, d = idx % DD;
    const float* xb = x + (size_t)b * NN * DD + d;
    float cls = xb[0], s = 0.f, s2 = 0.f;
    #pragma unroll 4
    for (int n = 0; n < NN; n++) { float v = xb[(size_t)n * DD]; s += v; s2 += v * v; }
    float mean = s / (float)NN;
    g_z[b * CIN + d] = cls;
    g_z[b * CIN + 384 + d] = mean;
    g_z[b * CIN + 768 + d] = s2 / (float)NN - mean * mean;
}

__global__ void k_build_uv(const float* __restrict__ Lb, const float* __restrict__ Rb) {
    int idx = blockIdx.x * blockDim.x + threadIdx.x;
    int d = idx >> 7, j = idx & 127, k = j >> 4, t = j & 15;
    if (t < 8) {
        g_U[d * 128 + j] = Lb[(k * DD + d) * 8 + t];
        g_V[d * 128 + j] = Rb[(k * DD + d) * 8 + t];
    } else {
        g_U[d * 128 + j] = -Rb[(k * DD + d) * 8 + t - 8];
        g_V[d * 128 + j] =  Lb[(k * DD + d) * 8 + t - 8];
    }
}

__global__ void k_norms(const float* __restrict__ Lb, const float* __restrict__ Rb) {
    int k = blockIdx.x, t = threadIdx.x;
    int which = t / 64, e = t % 64, i = e / 8, j = e % 8;
    __shared__ float gm[3][8][8];
    __shared__ float red[192];
    if (t < 192) {
        const float* Ap = (which == 0) ? Lb : Rb;
        const float* Bp = (which == 1) ? Rb : Lb;
        float acc = 0.f;
        for (int d = 0; d < DD; d++) acc += Ap[(k * DD + d) * 8 + i] * Bp[(k * DD + d) * 8 + j];
        gm[which][i][j] = acc;
    }
    __syncthreads();
    float part = 0.f;
    if (t < 64) part = 2.f * (gm[0][i][j] * gm[1][i][j] - gm[2][i][j] * gm[2][j][i]);
    red[t] = part;
    __syncthreads();
    if (t == 0) {
        float s = 0.f;
        for (int q = 0; q < 64; q++) s += red[q];
        g_nrm[k] = fmaxf(sqrtf(s), 1e-6f);
    }
}

__global__ void k_P() {
    int idx = blockIdx.x * 256 + threadIdx.x;
    int i = idx >> 7, j = idx & 127;
    float acc = 0.f;
    for (int d = 0; d < DD; d++) acc += g_V[d * 128 + i] * g_U[d * 128 + j];
    g_P[idx] = acc;
}

__global__ void k_T0(const float* __restrict__ W) {
    int idx = blockIdx.x * 256 + threadIdx.x;
    int j = idx / OUTD, o = idx % OUTD;
    float acc = 0.f;
    for (int d = 0; d < DD; d++) acc += g_V[d * 128 + j] * W[o * DD + d];
    g_T0[idx] = acc;
}

__global__ void k_ctrl(const float* __restrict__ w1, const float* __restrict__ b1,
                       const float* __restrict__ w_rot, const float* __restrict__ b_rot,
                       const float* __restrict__ w_rg, const float* __restrict__ b_rg,
                       const float* __restrict__ w_lg, const float* __restrict__ b_lg,
                       const float* __restrict__ w_sc, const float* __restrict__ b_sc,
                       const float* __restrict__ scale_basis, const float* __restrict__ ss_ptr) {
    int b = blockIdx.x, t = threadIdx.x;     // 128 threads
    int lane = t & 31, wid = t >> 5;
    __shared__ float zs[CIN];
    __shared__ float hs[HH];
    __shared__ float coef[KKB];
    for (int c = t; c < CIN; c += 128) zs[c] = g_z[b * CIN + c];
    __syncthreads();
    for (int to = wid; to < HH; to += 4) {
        const float* w = w1 + (size_t)to * CIN;
        float acc = 0.f;
        for (int c = lane; c < CIN; c += 32) acc += zs[c] * w[c];
        #pragma unroll
        for (int off = 16; off; off >>= 1) acc += __shfl_down_sync(0xFFFFFFFFu, acc, off);
        if (lane == 0) {
            float xg = acc + b1[to];
            float x3 = xg * xg * xg;
            hs[to] = 0.5f * xg * (1.f + tanhf(0.7978845608028654f * (xg + 0.044715f * x3)));
        }
    }
    __syncthreads();
    if (t < 8) {
        float acc = b_rot[t];
        for (int c = 0; c < HH; c++) acc += hs[c] * w_rot[t * HH + c];
        g_s[b * 8 + t] = 0.5f * tanhf(acc) / g_nrm[t];
    } else if (t == 8) {
        float acc = b_rg[0];
        for (int c = 0; c < HH; c++) acc += hs[c] * w_rg[c];
        g_g2[b] = 2.f / (1.f + expf(-acc));
    } else if (t == 9) {
        float acc = b_lg[0];
        for (int c = 0; c < HH; c++) acc += hs[c] * w_lg[c];
        g_lg[b] = 1.f / (1.f + expf(-acc));
    } else if (t >= 16 && t < 24) {
        int k = t - 16;
        float acc = b_sc[k];
        for (int c = 0; c < HH; c++) acc += hs[c] * w_sc[k * HH + c];
        coef[k] = tanhf(acc);
    }
    __syncthreads();
    float ss = ss_ptr[0];
    for (int o = t; o < OUTD; o += 128) {
        float acc = 0.f;
        for (int k = 0; k < KKB; k++) acc += coef[k] * scale_basis[k * OUTD + o];
        g_scale[b * OUTD + o] = 1.f + ss * tanhf(acc);
    }
}

// ---- fused LU + solve: g_Sinv = D * S^-1, all in shared, solves sync-free ----
#define LUP 129
#define LUSOLVE_SMEM (2 * 128 * LUP * 4)
__global__ void __launch_bounds__(128) k_lusolve() {
    extern __shared__ float smf[];
    float* a = smf;                 // LU, 128 x 129
    float* y = smf + 128 * LUP;     // solve workspace, 128 x 129
    __shared__ float sb[8];
    int b = blockIdx.x, i = threadIdx.x;    // 128 threads
    if (i < 8) sb[i] = g_s[b * 8 + i];
    __syncthreads();
    for (int q = 0; q < 128; q++)
        a[i * LUP + q] = (i == q ? 1.f : 0.f) - g_P[i * 128 + q] * sb[q >> 4];
    for (int p = 0; p < 127; p++) {
        __syncthreads();
        if (i > p) {
            float l = a[i * LUP + p] / a[p * LUP + p];
            a[i * LUP + p] = l;
            for (int q = p + 1; q < 128; q++) a[i * LUP + q] -= l * a[p * LUP + q];
        }
    }
    __syncthreads();
    // thread i owns column i of the solve; no cross-thread deps.
    for (int p = 0; p < 128; p++) {
        float a0 = 0.f, a1 = 0.f, a2 = 0.f, a3 = 0.f;
        const float* row = a + p * LUP;
        int q = 0;
        for (; q + 3 < p; q += 4) {
            a0 += row[q] * y[q * LUP + i];
            a1 += row[q + 1] * y[(q + 1) * LUP + i];
            a2 += row[q + 2] * y[(q + 2) * LUP + i];
            a3 += row[q + 3] * y[(q + 3) * LUP + i];
        }
        for (; q < p; q++) a0 += row[q] * y[q * LUP + i];
        y[p * LUP + i] = ((p == i) ? 1.f : 0.f) - (a0 + a1) - (a2 + a3);
    }
    for (int p = 127; p >= 0; p--) {
        float a0 = 0.f, a1 = 0.f, a2 = 0.f, a3 = 0.f;
        const float* row = a + p * LUP;
        int q = p + 1;
        for (; q + 3 < 128; q += 4) {
            a0 += row[q] * y[q * LUP + i];
            a1 += row[q + 1] * y[(q + 1) * LUP + i];
            a2 += row[q + 2] * y[(q + 2) * LUP + i];
            a3 += row[q + 3] * y[(q + 3) * LUP + i];
        }
        for (; q < 128; q++) a0 += row[q] * y[q * LUP + i];
        y[p * LUP + i] = (y[p * LUP + i] - (a0 + a1) - (a2 + a3)) / row[p];
    }
    float* sv = g_Sinv + (size_t)b * 128 * 128;
    for (int p = 0; p < 128; p++)
        sv[p * 128 + i] = sb[p >> 4] * y[p * LUP + i];      // D * S^-1
}

// E = U * (D * Sinv)  (384 x 128, K=128)
__global__ void __launch_bounds__(256) k_E() {
    int b = blockIdx.z, d0 = blockIdx.y * 128;
    __shared__ __align__(16) float As[16][132];
    __shared__ __align__(16) float Bs[16][132];
    int tid = threadIdx.x, tx = tid & 15, ty = tid >> 4;
    const float* Sv = g_Sinv + (size_t)b * 128 * 128;
    float acc[8][8] = {};
    int ar = tid >> 2, ac = (tid & 3) * 4;
    for (int k0 = 0; k0 < 128; k0 += 16) {
        #pragma unroll
        for (int h = 0; h < 2; h++) {
            int d = d0 + ar + h * 64;
            float4 v = *(const float4*)(g_U + (size_t)d * 128 + k0 + ac);
            As[ac + 0][ar + h * 64] = v.x;
            As[ac + 1][ar + h * 64] = v.y;
            As[ac + 2][ar + h * 64] = v.z;
            As[ac + 3][ar + h * 64] = v.w;
        }
        #pragma unroll
        for (int i2 = 0; i2 < 2; i2++) {
            int idx = tid + i2 * 256;
            int r = idx >> 5, cc = (idx & 31) * 4;
            *(float4*)&Bs[r][cc] = *(const float4*)(Sv + (size_t)(k0 + r) * 128 + cc);
        }
        __syncthreads();
        #pragma unroll
        for (int kk = 0; kk < 16; kk++) {
            float av[8], bv[8];
            *(float4*)&av[0] = *(const float4*)&As[kk][ty * 8];
            *(float4*)&av[4] = *(const float4*)&As[kk][ty * 8 + 4];
            *(float4*)&bv[0] = *(const float4*)&Bs[kk][tx * 8];
            *(float4*)&bv[4] = *(const float4*)&Bs[kk][tx * 8 + 4];
            #pragma unroll
            for (int i = 0; i < 8; i++)
                #pragma unroll
                for (int j = 0; j < 8; j++) acc[i][j] += av[i] * bv[j];
        }
        __syncthreads();
    }
    #pragma unroll
    for (int i = 0; i < 8; i++) {
        float* erow = g_E + ((size_t)b * DD + d0 + ty * 8 + i) * 128 + tx * 8;
        *(float4*)&erow[0] = *(float4*)&acc[i][0];
        *(float4*)&erow[4] = *(float4*)&acc[i][4];
    }
}

// WeffT[b][o][d] = W[o][d] + g2*(E@T0)[d][o]  -> bf16 hi/lo, K-major
__global__ void __launch_bounds__(256) k_weffT(const float* __restrict__ W) {
    int b = blockIdx.z, o0 = blockIdx.y * 128, d0 = blockIdx.x * 128;
    __shared__ __align__(16) float As[16][132];
    __shared__ __align__(16) float Bs[16][132];
    int tid = threadIdx.x, tx = tid & 15, ty = tid >> 4;
    const float* Eb = g_E + (size_t)b * DD * 128;
    float acc[8][8] = {};
    int ar = tid >> 2, ac = (tid & 3) * 4;
    for (int k0 = 0; k0 < 128; k0 += 16) {
        #pragma unroll
        for (int i2 = 0; i2 < 2; i2++) {
            int idx = tid + i2 * 256;
            int r = idx >> 5, cc = (idx & 31) * 4;
            *(float4*)&As[r][cc] = *(const float4*)(g_T0 + (size_t)(k0 + r) * OUTD + o0 + cc);
        }
        #pragma unroll
        for (int h = 0; h < 2; h++) {
            int d = d0 + ar + h * 64;
            float4 v = *(const float4*)(Eb + (size_t)d * 128 + k0 + ac);
            Bs[ac + 0][ar + h * 64] = v.x;
            Bs[ac + 1][ar + h * 64] = v.y;
            Bs[ac + 2][ar + h * 64] = v.z;
            Bs[ac + 3][ar + h * 64] = v.w;
        }
        __syncthreads();
        #pragma unroll
        for (int kk = 0; kk < 16; kk++) {
            float av[8], bv[8];
            *(float4*)&av[0] = *(const float4*)&As[kk][ty * 8];
            *(float4*)&av[4] = *(const float4*)&As[kk][ty * 8 + 4];
            *(float4*)&bv[0] = *(const float4*)&Bs[kk][tx * 8];
            *(float4*)&bv[4] = *(const float4*)&Bs[kk][tx * 8 + 4];
            #pragma unroll
            for (int i = 0; i < 8; i++)
                #pragma unroll
                for (int j = 0; j < 8; j++) acc[i][j] += av[i] * bv[j];
        }
        __syncthreads();
    }
    float g = g_g2[b];
    #pragma unroll
    for (int i = 0; i < 8; i++) {
        int o = o0 + ty * 8 + i;
        const float* wrow = W + (size_t)o * DD + d0 + tx * 8;
        __align__(16) __nv_bfloat16 hb[8], lb[8];
        #pragma unroll
        for (int j = 0; j < 8; j++) {
            float v = wrow[j] + g * acc[i][j];
            __nv_bfloat16 h = __float2bfloat16(v);
            hb[j] = h;
            lb[j] = __float2bfloat16(v - __bfloat162float(h));
        }
        size_t off = ((size_t)b * OUTD + o) * DD + d0 + tx * 8;
        *(uint4*)(g_WTh + off) = *(uint4*)hb;
        *(uint4*)(g_WTl + off) = *(uint4*)lb;
    }
}

__global__ void k_lm(const float* __restrict__ x, const float* __restrict__ ker) {
    int by = blockIdx.x;
    int b = by >> 5, y = by & 31, d = threadIdx.x;
    const float* xb = x + (size_t)b * NN * DD;
    float lg = g_lg[b];
    if (y == 0) {
        float v = xb[d];
        __nv_bfloat16 h = __float2bfloat16(v);
        g_lmh[(size_t)b * NN * DD + d] = h;
        g_lml[(size_t)b * NN * DD + d] = __float2bfloat16(v - __bfloat162float(h));
    }
    float k00 = ker[d * 9 + 0], k01 = ker[d * 9 + 1], k02 = ker[d * 9 + 2];
    float k10 = ker[d * 9 + 3], k11 = ker[d * 9 + 4], k12 = ker[d * 9 + 5];
    float k20 = ker[d * 9 + 6], k21 = ker[d * 9 + 7], k22 = ker[d * 9 + 8];
    bool up = (y > 0), dn = (y < 31);
    float ua = 0.f, ma = 0.f, la = 0.f, ub, mb, mc, lb, uc, lc;
    ub = up ? xb[(size_t)(1 + (y - 1) * 32) * DD + d] : 0.f;
    mb = xb[(size_t)(1 + y * 32) * DD + d];
    lb = dn ? xb[(size_t)(1 + (y + 1) * 32) * DD + d] : 0.f;
    for (int xx = 0; xx < 32; xx++) {
        if (xx < 31) {
            uc = up ? xb[(size_t)(1 + (y - 1) * 32 + xx + 1) * DD + d] : 0.f;
            mc = xb[(size_t)(1 + y * 32 + xx + 1) * DD + d];
            lc = dn ? xb[(size_t)(1 + (y + 1) * 32 + xx + 1) * DD + d] : 0.f;
        } else { uc = mc = lc = 0.f; }
        float conv = ua * k00 + ub * k01 + uc * k02 + ma * k10 + mb * k11 + mc * k12
                   + la * k20 + lb * k21 + lc * k22;
        float v = mb + lg * (conv - mb);
        size_t oi = ((size_t)b * NN + 1 + y * 32 + xx) * DD + d;
        __nv_bfloat16 h = __float2bfloat16(v);
        g_lmh[oi] = h;
        g_lml[oi] = __float2bfloat16(v - __bfloat162float(h));
        ua = ub; ub = uc; ma = mb; mb = mc; la = lb; lb = lc;
    }
}

// ---------------- main GEMM: fused hi/lo, 4 tiles per chunk, rows 0..1023 ----------------
#define BK 32
#define ROWB 80
#define TILEB (128 * ROWB)      // 10240 B
#define STAGEB (4 * TILEB)      // 40960 B
#define NCH 12
#define GEMM_SMEM (2 * STAGEB)  // 81920 B dynamic

__device__ __forceinline__ void cp16(uint32_t dst, const void* src) {
    asm volatile("cp.async.cg.shared.global [%0], [%1], 16;" :: "r"(dst), "l"(src) : "memory");
}

__global__ void __launch_bounds__(256, 2) k_gemm_mma(const float* __restrict__ bias,
                                                     float* __restrict__ out) {
    extern __shared__ __align__(16) unsigned char sm[];
    __shared__ float s_bias[128], s_scale[128];
    int b = blockIdx.z, m0 = blockIdx.y * 128, n0 = blockIdx.x * 128;
    int tid = threadIdx.x, lane = tid & 31, wid = tid >> 5;
    int wm = wid & 1, wn = wid >> 1;          // 2 (m) x 4 (n) warps

    if (tid < 128) {
        s_bias[tid] = bias[n0 + tid];
        s_scale[tid] = g_scale[b * OUTD + n0 + tid];
    }

    uint32_t smb = smem_u32(sm);
    float acc[4][4][4];
    #pragma unroll
    for (int i = 0; i < 4; i++)
        #pragma unroll
        for (int j = 0; j < 4; j++)
            #pragma unroll
            for (int q = 0; q < 4; q++) acc[i][j][q] = 0.f;

    int ci0 = tid, ci1 = tid + 256;
    int r0 = ci0 >> 2, ch0 = ci0 & 3;
    int r1 = ci1 >> 2, ch1 = ci1 & 3;
    size_t aoff0 = ((size_t)b * NN + m0 + r0) * DD;
    size_t aoff1 = ((size_t)b * NN + m0 + r1) * DD;
    size_t boff0 = ((size_t)b * OUTD + n0 + r0) * DD;
    size_t boff1 = ((size_t)b * OUTD + n0 + r1) * DD;

    #define LOAD_CHUNK(c, s) do { \
        int k0 = (c) * BK; \
        uint32_t Ah = smb + (uint32_t)(s) * STAGEB; \
        uint32_t Al = Ah + TILEB, Bh = Ah + 2 * TILEB, Bl = Ah + 3 * TILEB; \
        cp16(Ah + r0 * ROWB + ch0 * 16, g_lmh + aoff0 + k0 + ch0 * 8); \
        cp16(Ah + r1 * ROWB + ch1 * 16, g_lmh + aoff1 + k0 + ch1 * 8); \
        cp16(Al + r0 * ROWB + ch0 * 16, g_lml + aoff0 + k0 + ch0 * 8); \
        cp16(Al + r1 * ROWB + ch1 * 16, g_lml + aoff1 + k0 + ch1 * 8); \
        cp16(Bh + r0 * ROWB + ch0 * 16, g_WTh + boff0 + k0 + ch0 * 8); \
        cp16(Bh + r1 * ROWB + ch1 * 16, g_WTh + boff1 + k0 + ch1 * 8); \
        cp16(Bl + r0 * ROWB + ch0 * 16, g_WTl + boff0 + k0 + ch0 * 8); \
        cp16(Bl + r1 * ROWB + ch1 * 16, g_WTl + boff1 + k0 + ch1 * 8); \
    } while (0)

    #define LDMA(dst, base, mf) do { \
        uint32_t addr = (base) + (uint32_t)((wm * 64 + (mf) * 16 + (lane & 15)) * ROWB \
                      + (kstep * 2 + (lane >> 4)) * 16); \
        asm volatile("ldmatrix.sync.aligned.m8n8.x4.shared.b16 {%0,%1,%2,%3}, [%4];" \
            : "=r"((dst)[0]), "=r"((dst)[1]), "=r"((dst)[2]), "=r"((dst)[3]) : "r"(addr)); \
    } while (0)

    #define LDMB(dst, base) do { \
        int g = lane >> 3; \
        _Pragma("unroll") \
        for (int nf2 = 0; nf2 < 2; nf2++) { \
            uint32_t addr = (base) + (uint32_t)((wn * 32 + nf2 * 16 + ((g >> 1) << 3) + (lane & 7)) * ROWB \
                          + (kstep * 2 + (g & 1)) * 16); \
            uint32_t q0, q1, q2, q3; \
            asm volatile("ldmatrix.sync.aligned.m8n8.x4.shared.b16 {%0,%1,%2,%3}, [%4];" \
                : "=r"(q0), "=r"(q1), "=r"(q2), "=r"(q3) : "r"(addr)); \
            (dst)[nf2 * 2][0] = q0; (dst)[nf2 * 2][1] = q1; \
            (dst)[nf2 * 2 + 1][0] = q2; (dst)[nf2 * 2 + 1][1] = q3; \
        } \
    } while (0)

    #define MMAS(af, bfr) do { \
        _Pragma("unroll") \
        for (int mf = 0; mf < 4; mf++) \
            _Pragma("unroll") \
            for (int nf = 0; nf < 4; nf++) { \
                asm volatile( \
                    "mma.sync.aligned.m16n8k16.row.col.f32.bf16.bf16.f32 " \
                    "{%0,%1,%2,%3}, {%4,%5,%6,%7}, {%8,%9}, {%0,%1,%2,%3};" \
                    : "+f"(acc[mf][nf][0]), "+f"(acc[mf][nf][1]), \
                      "+f"(acc[mf][nf][2]), "+f"(acc[mf][nf][3]) \
                    : "r"((af)[mf][0]), "r"((af)[mf][1]), "r"((af)[mf][2]), "r"((af)[mf][3]), \
                      "r"((bfr)[nf][0]), "r"((bfr)[nf][1])); \
            } \
    } while (0)

    LOAD_CHUNK(0, 0);
    asm volatile("cp.async.commit_group;" ::: "memory");

    for (int c = 0; c < NCH; c++) {
        if (c + 1 < NCH) {
            LOAD_CHUNK(c + 1, (c + 1) & 1);
            asm volatile("cp.async.commit_group;" ::: "memory");
            asm volatile("cp.async.wait_group 1;" ::: "memory");
        } else {
            asm volatile("cp.async.wait_group 0;" ::: "memory");
        }
        __syncthreads();

        uint32_t Ah = smb + (uint32_t)(c & 1) * STAGEB;
        uint32_t Al = Ah + TILEB, Bh = Ah + 2 * TILEB, Bl = Ah + 3 * TILEB;
        #pragma unroll
        for (int kstep = 0; kstep < 2; kstep++) {
            uint32_t ah[4][4], bh[4][2];
            #pragma unroll
            for (int mf = 0; mf < 4; mf++) LDMA(ah[mf], Ah, mf);
            LDMB(bh, Bh);
            MMAS(ah, bh);
            {
                uint32_t bl[4][2];
                LDMB(bl, Bl);
                MMAS(ah, bl);
            }
            {
                uint32_t al[4][4];
                #pragma unroll
                for (int mf = 0; mf < 4; mf++) LDMA(al[mf], Al, mf);
                MMAS(al, bh);
            }
        }
        __syncthreads();
    }

    int gr = lane >> 2, gc = (lane & 3) * 2;
    #pragma unroll
    for (int mf = 0; mf < 4; mf++) {
        #pragma unroll
        for (int nf = 0; nf < 4; nf++) {
            int nl = wn * 32 + nf * 8 + gc;
            float b0 = s_bias[nl], b1 = s_bias[nl + 1];
            float sc0 = s_scale[nl], sc1 = s_scale[nl + 1];
            int mrow = m0 + wm * 64 + mf * 16 + gr;
            float2 v0 = make_float2((acc[mf][nf][0] + b0) * sc0, (acc[mf][nf][1] + b1) * sc1);
            *(float2*)(out + ((size_t)b * NN + mrow) * OUTD + n0 + nl) = v0;
            float2 v1 = make_float2((acc[mf][nf][2] + b0) * sc0, (acc[mf][nf][3] + b1) * sc1);
            *(float2*)(out + ((size_t)b * NN + mrow + 8) * OUTD + n0 + nl) = v1;
        }
    }
}

// row 1024 (last token) per batch
__global__ void k_lastrow(const float* __restrict__ bias, float* __restrict__ out) {
    int b = blockIdx.x, o = threadIdx.x;    // 384 threads
    __shared__ float av[DD];
    size_t lro = ((size_t)b * NN + NN - 1) * DD;
    for (int d = o; d < DD; d += 384)
        av[d] = __bfloat162float(g_lmh[lro + d]) + __bfloat162float(g_lml[lro + d]);
    __syncthreads();
    const __nv_bfloat162* wh = (const __nv_bfloat162*)(g_WTh + ((size_t)b * OUTD + o) * DD);
    const __nv_bfloat162* wl = (const __nv_bfloat162*)(g_WTl + ((size_t)b * OUTD + o) * DD);
    float acc = 0.f;
    #pragma unroll 4
    for (int d2 = 0; d2 < DD / 2; d2++) {
        float2 h = __bfloat1622float2(wh[d2]);
        float2 l = __bfloat1622float2(wl[d2]);
        acc += av[d2 * 2] * (h.x + l.x) + av[d2 * 2 + 1] * (h.y + l.y);
    }
    out[lro / DD * OUTD + o] = (acc + bias[o]) * g_scale[b * OUTD + o];
}

extern "C" void kernel_launch(void* const* d_in, const int* in_sizes, int n_in,
                              void* d_out, int out_size) {
    const float* x      = (const float*)d_in[0];
    const float* W      = (const float*)d_in[1];
    const float* bias   = (const float*)d_in[2];
    const float* Lb     = (const float*)d_in[3];
    const float* Rb     = (const float*)d_in[4];
    const float* sbasis = (const float*)d_in[5];
    const float* ss     = (const float*)d_in[6];
    const float* dwk    = (const float*)d_in[7];
    const float* w1     = (const float*)d_in[8];
    const float* b1     = (const float*)d_in[9];
    const float* w_rot  = (const float*)d_in[10];
    const float* b_rot  = (const float*)d_in[11];
    const float* w_rg   = (const float*)d_in[12];
    const float* b_rg   = (const float*)d_in[13];
    const float* w_lg   = (const float*)d_in[14];
    const float* b_lg   = (const float*)d_in[15];
    const float* w_sc   = (const float*)d_in[16];
    const float* b_sc   = (const float*)d_in[17];
    float* out = (float*)d_out;

    static int attr_set = 0;
    if (!attr_set) {
        cudaFuncSetAttribute(k_lusolve, cudaFuncAttributeMaxDynamicSharedMemorySize, LUSOLVE_SMEM);
        cudaFuncSetAttribute(k_gemm_mma, cudaFuncAttributeMaxDynamicSharedMemorySize, GEMM_SMEM);
        attr_set = 1;
    }

    k_stats<<<(BB * DD) / 128, 128>>>(x);
    k_build_uv<<<(DD * 128) / 256, 256>>>(Lb, Rb);
    k_norms<<<KKB, 192>>>(Lb, Rb);
    k_P<<<(128 * 128) / 256, 256>>>();
    k_T0<<<(128 * OUTD) / 256, 256>>>(W);
    k_ctrl<<<BB, 128>>>(w1, b1, w_rot, b_rot, w_rg, b_rg, w_lg, b_lg, w_sc, b_sc, sbasis, ss);
    k_lusolve<<<BB, 128, LUSOLVE_SMEM>>>();
    k_E<<<dim3(1, 3, BB), 256>>>();
    k_weffT<<<dim3(3, 3, BB), 256>>>(W);
    k_lm<<<BB * 32, 384>>>(x, dwk);
    k_gemm_mma<<<dim3(3, 8, BB), 256, GEMM_SMEM>>>(bias, out);
    k_lastrow<<<BB, 384>>>(bias, out);
}

// round 7
// speedup vs baseline: 1.8699x; 1.2294x over previous
#include <cuda_runtime.h>
#include <cuda_bf16.h>
#include <math.h>
#include <stdint.h>

#define BB 64
#define NN 1025
#define DD 384
#define KKB 8
#define HH 128
#define CIN 1152
#define OUTD 384

__device__ float g_z[BB * CIN];
__device__ float g_U[DD * 128];
__device__ float g_V[DD * 128];
__device__ float g_nrm[KKB];
__device__ float g_P[128 * 128];
__device__ float g_T0[128 * OUTD];
__device__ float g_s[BB * KKB];
__device__ float g_g2[BB];
__device__ float g_lg[BB];
__device__ float g_scale[BB * OUTD];
__device__ float g_Sinv[BB * 128 * 128];   // D * S^-1
__device__ float g_E[BB * DD * 128];
__device__ __nv_bfloat16 g_WTh[(size_t)BB * OUTD * DD];
__device__ __nv_bfloat16 g_WTl[(size_t)BB * OUTD * DD];
__device__ __nv_bfloat16 g_lmh[(size_t)BB * NN * DD];
__device__ __nv_bfloat16 g_lml[(size_t)BB * NN * DD];

__device__ __forceinline__ uint32_t smem_u32(const void* p) {
    return (uint32_t)__cvta_generic_to_shared(p);
}

__global__ void k_stats(const float* __restrict__ x) {
    int idx = blockIdx.x * blockDim.x + threadIdx.x;
    int b = idx / DD, d = idx % DD;
    const float* xb = x + (size_t)b * NN * DD + d;
    float cls = xb[0], s = 0.f, s2 = 0.f;
    #pragma unroll 8
    for (int n = 0; n < NN; n++) { float v = xb[(size_t)n * DD]; s += v; s2 += v * v; }
    float mean = s / (float)NN;
    g_z[b * CIN + d] = cls;
    g_z[b * CIN + 384 + d] = mean;
    g_z[b * CIN + 768 + d] = s2 / (float)NN - mean * mean;
}

__global__ void k_build_uv(const float* __restrict__ Lb, const float* __restrict__ Rb) {
    int idx = blockIdx.x * blockDim.x + threadIdx.x;
    int d = idx >> 7, j = idx & 127, k = j >> 4, t = j & 15;
    if (t < 8) {
        g_U[d * 128 + j] = Lb[(k * DD + d) * 8 + t];
        g_V[d * 128 + j] = Rb[(k * DD + d) * 8 + t];
    } else {
        g_U[d * 128 + j] = -Rb[(k * DD + d) * 8 + t - 8];
        g_V[d * 128 + j] =  Lb[(k * DD + d) * 8 + t - 8];
    }
}

__global__ void k_norms(const float* __restrict__ Lb, const float* __restrict__ Rb) {
    int k = blockIdx.x, t = threadIdx.x;
    int which = t / 64, e = t % 64, i = e / 8, j = e % 8;
    __shared__ float gm[3][8][8];
    __shared__ float red[192];
    if (t < 192) {
        const float* Ap = (which == 0) ? Lb : Rb;
        const float* Bp = (which == 1) ? Rb : Lb;
        float acc = 0.f;
        #pragma unroll 8
        for (int d = 0; d < DD; d++) acc += Ap[(k * DD + d) * 8 + i] * Bp[(k * DD + d) * 8 + j];
        gm[which][i][j] = acc;
    }
    __syncthreads();
    float part = 0.f;
    if (t < 64) part = 2.f * (gm[0][i][j] * gm[1][i][j] - gm[2][i][j] * gm[2][j][i]);
    red[t] = part;
    __syncthreads();
    if (t == 0) {
        float s = 0.f;
        for (int q = 0; q < 64; q++) s += red[q];
        g_nrm[k] = fmaxf(sqrtf(s), 1e-6f);
    }
}

__global__ void k_P() {
    int idx = blockIdx.x * 256 + threadIdx.x;
    int i = idx >> 7, j = idx & 127;
    float acc = 0.f;
    #pragma unroll 8
    for (int d = 0; d < DD; d++) acc += g_V[d * 128 + i] * g_U[d * 128 + j];
    g_P[idx] = acc;
}

// T0[j][o] = sum_d V[d][j] * W[o][d]   (128 x 384), tiled + coalesced W
__global__ void __launch_bounds__(256) k_T0(const float* __restrict__ W) {
    int o0 = blockIdx.x * 128;
    __shared__ __align__(16) float As[16][132];   // [k][j] = V[k0+k][j]
    __shared__ float Bs[16][132];                 // [k][o] = W[o0+o][k0+k]
    int tid = threadIdx.x, tx = tid & 15, ty = tid >> 4;
    float acc[8][8] = {};
    int ro = tid >> 1, co = (tid & 1) * 8;
    for (int k0 = 0; k0 < DD; k0 += 16) {
        #pragma unroll
        for (int i2 = 0; i2 < 2; i2++) {
            int idx = tid + i2 * 256;
            int r = idx >> 5, c = (idx & 31) * 4;
            *(float4*)&As[r][c] = *(const float4*)(g_V + (size_t)(k0 + r) * 128 + c);
        }
        #pragma unroll
        for (int h = 0; h < 2; h++) {
            float4 w = *(const float4*)(W + (size_t)(o0 + ro) * DD + k0 + co + h * 4);
            Bs[co + h * 4 + 0][ro] = w.x;
            Bs[co + h * 4 + 1][ro] = w.y;
            Bs[co + h * 4 + 2][ro] = w.z;
            Bs[co + h * 4 + 3][ro] = w.w;
        }
        __syncthreads();
        #pragma unroll
        for (int kk = 0; kk < 16; kk++) {
            float av[8], bv[8];
            *(float4*)&av[0] = *(const float4*)&As[kk][ty * 8];
            *(float4*)&av[4] = *(const float4*)&As[kk][ty * 8 + 4];
            #pragma unroll
            for (int j = 0; j < 8; j++) bv[j] = Bs[kk][tx * 8 + j];
            #pragma unroll
            for (int i = 0; i < 8; i++)
                #pragma unroll
                for (int j = 0; j < 8; j++) acc[i][j] += av[i] * bv[j];
        }
        __syncthreads();
    }
    #pragma unroll
    for (int i = 0; i < 8; i++) {
        float* row = g_T0 + (size_t)(ty * 8 + i) * OUTD + o0 + tx * 8;
        *(float4*)&row[0] = *(float4*)&acc[i][0];
        *(float4*)&row[4] = *(float4*)&acc[i][4];
    }
}

__global__ void k_ctrl(const float* __restrict__ w1, const float* __restrict__ b1,
                       const float* __restrict__ w_rot, const float* __restrict__ b_rot,
                       const float* __restrict__ w_rg, const float* __restrict__ b_rg,
                       const float* __restrict__ w_lg, const float* __restrict__ b_lg,
                       const float* __restrict__ w_sc, const float* __restrict__ b_sc,
                       const float* __restrict__ scale_basis, const float* __restrict__ ss_ptr) {
    int b = blockIdx.x, t = threadIdx.x;
    int lane = t & 31, wid = t >> 5;
    __shared__ float zs[CIN];
    __shared__ float hs[HH];
    __shared__ float coef[KKB];
    for (int c = t; c < CIN; c += 128) zs[c] = g_z[b * CIN + c];
    __syncthreads();
    for (int to = wid; to < HH; to += 4) {
        const float* w = w1 + (size_t)to * CIN;
        float acc = 0.f;
        for (int c = lane; c < CIN; c += 32) acc += zs[c] * w[c];
        #pragma unroll
        for (int off = 16; off; off >>= 1) acc += __shfl_down_sync(0xFFFFFFFFu, acc, off);
        if (lane == 0) {
            float xg = acc + b1[to];
            float x3 = xg * xg * xg;
            hs[to] = 0.5f * xg * (1.f + tanhf(0.7978845608028654f * (xg + 0.044715f * x3)));
        }
    }
    __syncthreads();
    if (t < 8) {
        float acc = b_rot[t];
        for (int c = 0; c < HH; c++) acc += hs[c] * w_rot[t * HH + c];
        g_s[b * 8 + t] = 0.5f * tanhf(acc) / g_nrm[t];
    } else if (t == 8) {
        float acc = b_rg[0];
        for (int c = 0; c < HH; c++) acc += hs[c] * w_rg[c];
        g_g2[b] = 2.f / (1.f + expf(-acc));
    } else if (t == 9) {
        float acc = b_lg[0];
        for (int c = 0; c < HH; c++) acc += hs[c] * w_lg[c];
        g_lg[b] = 1.f / (1.f + expf(-acc));
    } else if (t >= 16 && t < 24) {
        int k = t - 16;
        float acc = b_sc[k];
        for (int c = 0; c < HH; c++) acc += hs[c] * w_sc[k * HH + c];
        coef[k] = tanhf(acc);
    }
    __syncthreads();
    float ss = ss_ptr[0];
    for (int o = t; o < OUTD; o += 128) {
        float acc = 0.f;
        for (int k = 0; k < KKB; k++) acc += coef[k] * scale_basis[k * OUTD + o];
        g_scale[b * OUTD + o] = 1.f + ss * tanhf(acc);
    }
}

#define LUP 129
#define LUSOLVE_SMEM (2 * 128 * LUP * 4)
__global__ void __launch_bounds__(128) k_lusolve() {
    extern __shared__ float smf[];
    float* a = smf;
    float* y = smf + 128 * LUP;
    __shared__ float sb[8];
    int b = blockIdx.x, i = threadIdx.x;
    if (i < 8) sb[i] = g_s[b * 8 + i];
    __syncthreads();
    for (int q = 0; q < 128; q++)
        a[i * LUP + q] = (i == q ? 1.f : 0.f) - g_P[i * 128 + q] * sb[q >> 4];
    for (int p = 0; p < 127; p++) {
        __syncthreads();
        if (i > p) {
            float l = a[i * LUP + p] / a[p * LUP + p];
            a[i * LUP + p] = l;
            for (int q = p + 1; q < 128; q++) a[i * LUP + q] -= l * a[p * LUP + q];
        }
    }
    __syncthreads();
    for (int p = 0; p < 128; p++) {
        float a0 = 0.f, a1 = 0.f, a2 = 0.f, a3 = 0.f;
        const float* row = a + p * LUP;
        int q = 0;
        for (; q + 3 < p; q += 4) {
            a0 += row[q] * y[q * LUP + i];
            a1 += row[q + 1] * y[(q + 1) * LUP + i];
            a2 += row[q + 2] * y[(q + 2) * LUP + i];
            a3 += row[q + 3] * y[(q + 3) * LUP + i];
        }
        for (; q < p; q++) a0 += row[q] * y[q * LUP + i];
        y[p * LUP + i] = ((p == i) ? 1.f : 0.f) - (a0 + a1) - (a2 + a3);
    }
    for (int p = 127; p >= 0; p--) {
        float a0 = 0.f, a1 = 0.f, a2 = 0.f, a3 = 0.f;
        const float* row = a + p * LUP;
        int q = p + 1;
        for (; q + 3 < 128; q += 4) {
            a0 += row[q] * y[q * LUP + i];
            a1 += row[q + 1] * y[(q + 1) * LUP + i];
            a2 += row[q + 2] * y[(q + 2) * LUP + i];
            a3 += row[q + 3] * y[(q + 3) * LUP + i];
        }
        for (; q < 128; q++) a0 += row[q] * y[q * LUP + i];
        y[p * LUP + i] = (y[p * LUP + i] - (a0 + a1) - (a2 + a3)) / row[p];
    }
    float* sv = g_Sinv + (size_t)b * 128 * 128;
    for (int p = 0; p < 128; p++)
        sv[p * 128 + i] = sb[p >> 4] * y[p * LUP + i];
}

__global__ void __launch_bounds__(256) k_E() {
    int b = blockIdx.z, d0 = blockIdx.y * 128;
    __shared__ __align__(16) float As[16][132];
    __shared__ __align__(16) float Bs[16][132];
    int tid = threadIdx.x, tx = tid & 15, ty = tid >> 4;
    const float* Sv = g_Sinv + (size_t)b * 128 * 128;
    float acc[8][8] = {};
    int ar = tid >> 2, ac = (tid & 3) * 4;
    for (int k0 = 0; k0 < 128; k0 += 16) {
        #pragma unroll
        for (int h = 0; h < 2; h++) {
            int d = d0 + ar + h * 64;
            float4 v = *(const float4*)(g_U + (size_t)d * 128 + k0 + ac);
            As[ac + 0][ar + h * 64] = v.x;
            As[ac + 1][ar + h * 64] = v.y;
            As[ac + 2][ar + h * 64] = v.z;
            As[ac + 3][ar + h * 64] = v.w;
        }
        #pragma unroll
        for (int i2 = 0; i2 < 2; i2++) {
            int idx = tid + i2 * 256;
            int r = idx >> 5, cc = (idx & 31) * 4;
            *(float4*)&Bs[r][cc] = *(const float4*)(Sv + (size_t)(k0 + r) * 128 + cc);
        }
        __syncthreads();
        #pragma unroll
        for (int kk = 0; kk < 16; kk++) {
            float av[8], bv[8];
            *(float4*)&av[0] = *(const float4*)&As[kk][ty * 8];
            *(float4*)&av[4] = *(const float4*)&As[kk][ty * 8 + 4];
            *(float4*)&bv[0] = *(const float4*)&Bs[kk][tx * 8];
            *(float4*)&bv[4] = *(const float4*)&Bs[kk][tx * 8 + 4];
            #pragma unroll
            for (int i = 0; i < 8; i++)
                #pragma unroll
                for (int j = 0; j < 8; j++) acc[i][j] += av[i] * bv[j];
        }
        __syncthreads();
    }
    #pragma unroll
    for (int i = 0; i < 8; i++) {
        float* erow = g_E + ((size_t)b * DD + d0 + ty * 8 + i) * 128 + tx * 8;
        *(float4*)&erow[0] = *(float4*)&acc[i][0];
        *(float4*)&erow[4] = *(float4*)&acc[i][4];
    }
}

__global__ void __launch_bounds__(256) k_weffT(const float* __restrict__ W) {
    int b = blockIdx.z, o0 = blockIdx.y * 128, d0 = blockIdx.x * 128;
    __shared__ __align__(16) float As[16][132];
    __shared__ __align__(16) float Bs[16][132];
    int tid = threadIdx.x, tx = tid & 15, ty = tid >> 4;
    const float* Eb = g_E + (size_t)b * DD * 128;
    float acc[8][8] = {};
    int ar = tid >> 2, ac = (tid & 3) * 4;
    for (int k0 = 0; k0 < 128; k0 += 16) {
        #pragma unroll
        for (int i2 = 0; i2 < 2; i2++) {
            int idx = tid + i2 * 256;
            int r = idx >> 5, cc = (idx & 31) * 4;
            *(float4*)&As[r][cc] = *(const float4*)(g_T0 + (size_t)(k0 + r) * OUTD + o0 + cc);
        }
        #pragma unroll
        for (int h = 0; h < 2; h++) {
            int d = d0 + ar + h * 64;
            float4 v = *(const float4*)(Eb + (size_t)d * 128 + k0 + ac);
            Bs[ac + 0][ar + h * 64] = v.x;
            Bs[ac + 1][ar + h * 64] = v.y;
            Bs[ac + 2][ar + h * 64] = v.z;
            Bs[ac + 3][ar + h * 64] = v.w;
        }
        __syncthreads();
        #pragma unroll
        for (int kk = 0; kk < 16; kk++) {
            float av[8], bv[8];
            *(float4*)&av[0] = *(const float4*)&As[kk][ty * 8];
            *(float4*)&av[4] = *(const float4*)&As[kk][ty * 8 + 4];
            *(float4*)&bv[0] = *(const float4*)&Bs[kk][tx * 8];
            *(float4*)&bv[4] = *(const float4*)&Bs[kk][tx * 8 + 4];
            #pragma unroll
            for (int i = 0; i < 8; i++)
                #pragma unroll
                for (int j = 0; j < 8; j++) acc[i][j] += av[i] * bv[j];
        }
        __syncthreads();
    }
    float g = g_g2[b];
    #pragma unroll
    for (int i = 0; i < 8; i++) {
        int o = o0 + ty * 8 + i;
        const float* wrow = W + (size_t)o * DD + d0 + tx * 8;
        __align__(16) __nv_bfloat16 hb[8], lb[8];
        #pragma unroll
        for (int j = 0; j < 8; j++) {
            float v = wrow[j] + g * acc[i][j];
            __nv_bfloat16 h = __float2bfloat16(v);
            hb[j] = h;
            lb[j] = __float2bfloat16(v - __bfloat162float(h));
        }
        size_t off = ((size_t)b * OUTD + o) * DD + d0 + tx * 8;
        *(uint4*)(g_WTh + off) = *(uint4*)hb;
        *(uint4*)(g_WTl + off) = *(uint4*)lb;
    }
}

__global__ void k_lm(const float* __restrict__ x, const float* __restrict__ ker) {
    int by = blockIdx.x;
    int b = by >> 5, y = by & 31, d = threadIdx.x;
    const float* xb = x + (size_t)b * NN * DD;
    float lg = g_lg[b];
    if (y == 0) {
        float v = xb[d];
        __nv_bfloat16 h = __float2bfloat16(v);
        g_lmh[(size_t)b * NN * DD + d] = h;
        g_lml[(size_t)b * NN * DD + d] = __float2bfloat16(v - __bfloat162float(h));
    }
    float k00 = ker[d * 9 + 0], k01 = ker[d * 9 + 1], k02 = ker[d * 9 + 2];
    float k10 = ker[d * 9 + 3], k11 = ker[d * 9 + 4], k12 = ker[d * 9 + 5];
    float k20 = ker[d * 9 + 6], k21 = ker[d * 9 + 7], k22 = ker[d * 9 + 8];
    bool up = (y > 0), dn = (y < 31);
    float ua = 0.f, ma = 0.f, la = 0.f, ub, mb, mc, lb, uc, lc;
    ub = up ? xb[(size_t)(1 + (y - 1) * 32) * DD + d] : 0.f;
    mb = xb[(size_t)(1 + y * 32) * DD + d];
    lb = dn ? xb[(size_t)(1 + (y + 1) * 32) * DD + d] : 0.f;
    for (int xx = 0; xx < 32; xx++) {
        if (xx < 31) {
            uc = up ? xb[(size_t)(1 + (y - 1) * 32 + xx + 1) * DD + d] : 0.f;
            mc = xb[(size_t)(1 + y * 32 + xx + 1) * DD + d];
            lc = dn ? xb[(size_t)(1 + (y + 1) * 32 + xx + 1) * DD + d] : 0.f;
        } else { uc = mc = lc = 0.f; }
        float conv = ua * k00 + ub * k01 + uc * k02 + ma * k10 + mb * k11 + mc * k12
                   + la * k20 + lb * k21 + lc * k22;
        float v = mb + lg * (conv - mb);
        size_t oi = ((size_t)b * NN + 1 + y * 32 + xx) * DD + d;
        __nv_bfloat16 h = __float2bfloat16(v);
        g_lmh[oi] = h;
        g_lml[oi] = __float2bfloat16(v - __bfloat162float(h));
        ua = ub; ub = uc; ma = mb; mb = mc; la = lb; lb = lc;
    }
}

#define BK 32
#define ROWB 80
#define TILEB (128 * ROWB)
#define STAGEB (4 * TILEB)
#define NCH 12
#define GEMM_SMEM (2 * STAGEB)

__device__ __forceinline__ void cp16(uint32_t dst, const void* src) {
    asm volatile("cp.async.cg.shared.global [%0], [%1], 16;" :: "r"(dst), "l"(src) : "memory");
}

__global__ void __launch_bounds__(256, 2) k_gemm_mma(const float* __restrict__ bias,
                                                     float* __restrict__ out) {
    extern __shared__ __align__(16) unsigned char sm[];
    __shared__ float s_bias[128], s_scale[128];
    int b = blockIdx.z, m0 = blockIdx.y * 128, n0 = blockIdx.x * 128;
    int tid = threadIdx.x, lane = tid & 31, wid = tid >> 5;
    int wm = wid & 1, wn = wid >> 1;

    if (tid < 128) {
        s_bias[tid] = bias[n0 + tid];
        s_scale[tid] = g_scale[b * OUTD + n0 + tid];
    }

    uint32_t smb = smem_u32(sm);
    float acc[4][4][4];
    #pragma unroll
    for (int i = 0; i < 4; i++)
        #pragma unroll
        for (int j = 0; j < 4; j++)
            #pragma unroll
            for (int q = 0; q < 4; q++) acc[i][j][q] = 0.f;

    int ci0 = tid, ci1 = tid + 256;
    int r0 = ci0 >> 2, ch0 = ci0 & 3;
    int r1 = ci1 >> 2, ch1 = ci1 & 3;
    size_t aoff0 = ((size_t)b * NN + m0 + r0) * DD;
    size_t aoff1 = ((size_t)b * NN + m0 + r1) * DD;
    size_t boff0 = ((size_t)b * OUTD + n0 + r0) * DD;
    size_t boff1 = ((size_t)b * OUTD + n0 + r1) * DD;

    #define LOAD_CHUNK(c, s) do { \
        int k0 = (c) * BK; \
        uint32_t Ah = smb + (uint32_t)(s) * STAGEB; \
        uint32_t Al = Ah + TILEB, Bh = Ah + 2 * TILEB, Bl = Ah + 3 * TILEB; \
        cp16(Ah + r0 * ROWB + ch0 * 16, g_lmh + aoff0 + k0 + ch0 * 8); \
        cp16(Ah + r1 * ROWB + ch1 * 16, g_lmh + aoff1 + k0 + ch1 * 8); \
        cp16(Al + r0 * ROWB + ch0 * 16, g_lml + aoff0 + k0 + ch0 * 8); \
        cp16(Al + r1 * ROWB + ch1 * 16, g_lml + aoff1 + k0 + ch1 * 8); \
        cp16(Bh + r0 * ROWB + ch0 * 16, g_WTh + boff0 + k0 + ch0 * 8); \
        cp16(Bh + r1 * ROWB + ch1 * 16, g_WTh + boff1 + k0 + ch1 * 8); \
        cp16(Bl + r0 * ROWB + ch0 * 16, g_WTl + boff0 + k0 + ch0 * 8); \
        cp16(Bl + r1 * ROWB + ch1 * 16, g_WTl + boff1 + k0 + ch1 * 8); \
    } while (0)

    #define LDMA(dst, base, mf) do { \
        uint32_t addr = (base) + (uint32_t)((wm * 64 + (mf) * 16 + (lane & 15)) * ROWB \
                      + (kstep * 2 + (lane >> 4)) * 16); \
        asm volatile("ldmatrix.sync.aligned.m8n8.x4.shared.b16 {%0,%1,%2,%3}, [%4];" \
            : "=r"((dst)[0]), "=r"((dst)[1]), "=r"((dst)[2]), "=r"((dst)[3]) : "r"(addr)); \
    } while (0)

    #define LDMB(dst, base) do { \
        int g = lane >> 3; \
        _Pragma("unroll") \
        for (int nf2 = 0; nf2 < 2; nf2++) { \
            uint32_t addr = (base) + (uint32_t)((wn * 32 + nf2 * 16 + ((g >> 1) << 3) + (lane & 7)) * ROWB \
                          + (kstep * 2 + (g & 1)) * 16); \
            uint32_t q0, q1, q2, q3; \
            asm volatile("ldmatrix.sync.aligned.m8n8.x4.shared.b16 {%0,%1,%2,%3}, [%4];" \
                : "=r"(q0), "=r"(q1), "=r"(q2), "=r"(q3) : "r"(addr)); \
            (dst)[nf2 * 2][0] = q0; (dst)[nf2 * 2][1] = q1; \
            (dst)[nf2 * 2 + 1][0] = q2; (dst)[nf2 * 2 + 1][1] = q3; \
        } \
    } while (0)

    #define MMAS(af, bfr) do { \
        _Pragma("unroll") \
        for (int mf = 0; mf < 4; mf++) \
            _Pragma("unroll") \
            for (int nf = 0; nf < 4; nf++) { \
                asm volatile( \
                    "mma.sync.aligned.m16n8k16.row.col.f32.bf16.bf16.f32 " \
                    "{%0,%1,%2,%3}, {%4,%5,%6,%7}, {%8,%9}, {%0,%1,%2,%3};" \
                    : "+f"(acc[mf][nf][0]), "+f"(acc[mf][nf][1]), \
                      "+f"(acc[mf][nf][2]), "+f"(acc[mf][nf][3]) \
                    : "r"((af)[mf][0]), "r"((af)[mf][1]), "r"((af)[mf][2]), "r"((af)[mf][3]), \
                      "r"((bfr)[nf][0]), "r"((bfr)[nf][1])); \
            } \
    } while (0)

    LOAD_CHUNK(0, 0);
    asm volatile("cp.async.commit_group;" ::: "memory");

    for (int c = 0; c < NCH; c++) {
        if (c + 1 < NCH) {
            LOAD_CHUNK(c + 1, (c + 1) & 1);
            asm volatile("cp.async.commit_group;" ::: "memory");
            asm volatile("cp.async.wait_group 1;" ::: "memory");
        } else {
            asm volatile("cp.async.wait_group 0;" ::: "memory");
        }
        __syncthreads();

        uint32_t Ah = smb + (uint32_t)(c & 1) * STAGEB;
        uint32_t Al = Ah + TILEB, Bh = Ah + 2 * TILEB, Bl = Ah + 3 * TILEB;
        #pragma unroll
        for (int kstep = 0; kstep < 2; kstep++) {
            uint32_t ah[4][4], bh[4][2];
            #pragma unroll
            for (int mf = 0; mf < 4; mf++) LDMA(ah[mf], Ah, mf);
            LDMB(bh, Bh);
            MMAS(ah, bh);
            {
                uint32_t bl[4][2];
                LDMB(bl, Bl);
                MMAS(ah, bl);
            }
            {
                uint32_t al[4][4];
                #pragma unroll
                for (int mf = 0; mf < 4; mf++) LDMA(al[mf], Al, mf);
                MMAS(al, bh);
            }
        }
        __syncthreads();
    }

    int gr = lane >> 2, gc = (lane & 3) * 2;
    #pragma unroll
    for (int mf = 0; mf < 4; mf++) {
        #pragma unroll
        for (int nf = 0; nf < 4; nf++) {
            int nl = wn * 32 + nf * 8 + gc;
            float b0 = s_bias[nl], b1 = s_bias[nl + 1];
            float sc0 = s_scale[nl], sc1 = s_scale[nl + 1];
            int mrow = m0 + wm * 64 + mf * 16 + gr;
            float2 v0 = make_float2((acc[mf][nf][0] + b0) * sc0, (acc[mf][nf][1] + b1) * sc1);
            *(float2*)(out + ((size_t)b * NN + mrow) * OUTD + n0 + nl) = v0;
            float2 v1 = make_float2((acc[mf][nf][2] + b0) * sc0, (acc[mf][nf][3] + b1) * sc1);
            *(float2*)(out + ((size_t)b * NN + mrow + 8) * OUTD + n0 + nl) = v1;
        }
    }
}

__global__ void k_lastrow(const float* __restrict__ bias, float* __restrict__ out) {
    int b = blockIdx.x, o = threadIdx.x;
    __shared__ float av[DD];
    size_t lro = ((size_t)b * NN + NN - 1) * DD;
    for (int d = o; d < DD; d += 384)
        av[d] = __bfloat162float(g_lmh[lro + d]) + __bfloat162float(g_lml[lro + d]);
    __syncthreads();
    const __nv_bfloat162* wh = (const __nv_bfloat162*)(g_WTh + ((size_t)b * OUTD + o) * DD);
    const __nv_bfloat162* wl = (const __nv_bfloat162*)(g_WTl + ((size_t)b * OUTD + o) * DD);
    float acc = 0.f;
    #pragma unroll 4
    for (int d2 = 0; d2 < DD / 2; d2++) {
        float2 h = __bfloat1622float2(wh[d2]);
        float2 l = __bfloat1622float2(wl[d2]);
        acc += av[d2 * 2] * (h.x + l.x) + av[d2 * 2 + 1] * (h.y + l.y);
    }
    out[lro / DD * OUTD + o] = (acc + bias[o]) * g_scale[b * OUTD + o];
}

// ---------------- launch with fork-join stream overlap ----------------
static cudaStream_t s1, s2;
static cudaEvent_t ev_fork, ev_norms, ev_s1done, ev_ctrl, ev_lm;

extern "C" void kernel_launch(void* const* d_in, const int* in_sizes, int n_in,
                              void* d_out, int out_size) {
    const float* x      = (const float*)d_in[0];
    const float* W      = (const float*)d_in[1];
    const float* bias   = (const float*)d_in[2];
    const float* Lb     = (const float*)d_in[3];
    const float* Rb     = (const float*)d_in[4];
    const float* sbasis = (const float*)d_in[5];
    const float* ss     = (const float*)d_in[6];
    const float* dwk    = (const float*)d_in[7];
    const float* w1     = (const float*)d_in[8];
    const float* b1     = (const float*)d_in[9];
    const float* w_rot  = (const float*)d_in[10];
    const float* b_rot  = (const float*)d_in[11];
    const float* w_rg   = (const float*)d_in[12];
    const float* b_rg   = (const float*)d_in[13];
    const float* w_lg   = (const float*)d_in[14];
    const float* b_lg   = (const float*)d_in[15];
    const float* w_sc   = (const float*)d_in[16];
    const float* b_sc   = (const float*)d_in[17];
    float* out = (float*)d_out;

    static int init_done = 0;
    if (!init_done) {
        cudaFuncSetAttribute(k_lusolve, cudaFuncAttributeMaxDynamicSharedMemorySize, LUSOLVE_SMEM);
        cudaFuncSetAttribute(k_gemm_mma, cudaFuncAttributeMaxDynamicSharedMemorySize, GEMM_SMEM);
        cudaStreamCreateWithFlags(&s1, cudaStreamNonBlocking);
        cudaStreamCreateWithFlags(&s2, cudaStreamNonBlocking);
        cudaEventCreateWithFlags(&ev_fork, cudaEventDisableTiming);
        cudaEventCreateWithFlags(&ev_norms, cudaEventDisableTiming);
        cudaEventCreateWithFlags(&ev_s1done, cudaEventDisableTiming);
        cudaEventCreateWithFlags(&ev_ctrl, cudaEventDisableTiming);
        cudaEventCreateWithFlags(&ev_lm, cudaEventDisableTiming);
        init_done = 1;
    }

    // fork s1 off the origin (null) stream
    cudaEventRecord(ev_fork, 0);
    cudaStreamWaitEvent(s1, ev_fork, 0);

    // stream s1: basis-side chain
    k_build_uv<<<(DD * 128) / 256, 256, 0, s1>>>(Lb, Rb);
    k_norms<<<KKB, 192, 0, s1>>>(Lb, Rb);
    cudaEventRecord(ev_norms, s1);
    k_P<<<(128 * 128) / 256, 256, 0, s1>>>();
    k_T0<<<3, 256, 0, s1>>>(W);
    cudaEventRecord(ev_s1done, s1);

    // origin stream: stats -> ctrl (needs norms)
    k_stats<<<(BB * DD) / 128, 128>>>(x);
    cudaStreamWaitEvent(0, ev_norms, 0);
    k_ctrl<<<BB, 128>>>(w1, b1, w_rot, b_rot, w_rg, b_rg, w_lg, b_lg, w_sc, b_sc, sbasis, ss);
    cudaEventRecord(ev_ctrl, 0);

    // stream s2: lm (needs ctrl's local_gate)
    cudaStreamWaitEvent(s2, ev_ctrl, 0);
    k_lm<<<BB * 32, 384, 0, s2>>>(x, dwk);
    cudaEventRecord(ev_lm, s2);

    // origin stream: lusolve (needs P) -> E -> weffT (needs T0)
    cudaStreamWaitEvent(0, ev_s1done, 0);
    k_lusolve<<<BB, 128, LUSOLVE_SMEM>>>();
    k_E<<<dim3(1, 3, BB), 256>>>();
    k_weffT<<<dim3(3, 3, BB), 256>>>(W);

    // join lm, then main GEMM + last row
    cudaStreamWaitEvent(0, ev_lm, 0);
    k_gemm_mma<<<dim3(3, 8, BB), 256, GEMM_SMEM>>>(bias, out);
    k_lastrow<<<BB, 384>>>(bias, out);
}

// round 8
// speedup vs baseline: 1.9904x; 1.0644x over previous
#include <cuda_runtime.h>
#include <cuda_fp16.h>
#include <math.h>
#include <stdint.h>

#define BB 64
#define NN 1025
#define DD 384
#define KKB 8
#define HH 128
#define CIN 1152
#define OUTD 384

__device__ float g_z[BB * CIN];
__device__ float g_U[DD * 128];
__device__ float g_V[DD * 128];
__device__ float g_nrm[KKB];
__device__ float g_P[128 * 128];
__device__ float g_T0[128 * OUTD];
__device__ float g_s[BB * KKB];
__device__ float g_g2[BB];
__device__ float g_lg[BB];
__device__ float g_scale[BB * OUTD];
__device__ float g_Sinv[BB * 128 * 128];   // D * S^-1
__device__ float g_E[BB * DD * 128];
__device__ __half g_WTh[(size_t)BB * OUTD * DD];
__device__ __half g_WTl[(size_t)BB * OUTD * DD];
__device__ __half g_lmh[(size_t)BB * NN * DD];

__device__ __forceinline__ uint32_t smem_u32(const void* p) {
    return (uint32_t)__cvta_generic_to_shared(p);
}

__global__ void k_stats(const float* __restrict__ x) {
    int idx = blockIdx.x * blockDim.x + threadIdx.x;
    int b = idx / DD, d = idx % DD;
    const float* xb = x + (size_t)b * NN * DD + d;
    float cls = xb[0], s = 0.f, s2 = 0.f;
    #pragma unroll 8
    for (int n = 0; n < NN; n++) { float v = xb[(size_t)n * DD]; s += v; s2 += v * v; }
    float mean = s / (float)NN;
    g_z[b * CIN + d] = cls;
    g_z[b * CIN + 384 + d] = mean;
    g_z[b * CIN + 768 + d] = s2 / (float)NN - mean * mean;
}

__global__ void k_build_uv(const float* __restrict__ Lb, const float* __restrict__ Rb) {
    int idx = blockIdx.x * blockDim.x + threadIdx.x;
    int d = idx >> 7, j = idx & 127, k = j >> 4, t = j & 15;
    if (t < 8) {
        g_U[d * 128 + j] = Lb[(k * DD + d) * 8 + t];
        g_V[d * 128 + j] = Rb[(k * DD + d) * 8 + t];
    } else {
        g_U[d * 128 + j] = -Rb[(k * DD + d) * 8 + t - 8];
        g_V[d * 128 + j] =  Lb[(k * DD + d) * 8 + t - 8];
    }
}

__global__ void k_norms(const float* __restrict__ Lb, const float* __restrict__ Rb) {
    int k = blockIdx.x, t = threadIdx.x;
    int which = t / 64, e = t % 64, i = e / 8, j = e % 8;
    __shared__ float gm[3][8][8];
    __shared__ float red[192];
    if (t < 192) {
        const float* Ap = (which == 0) ? Lb : Rb;
        const float* Bp = (which == 1) ? Rb : Lb;
        float acc = 0.f;
        #pragma unroll 8
        for (int d = 0; d < DD; d++) acc += Ap[(k * DD + d) * 8 + i] * Bp[(k * DD + d) * 8 + j];
        gm[which][i][j] = acc;
    }
    __syncthreads();
    float part = 0.f;
    if (t < 64) part = 2.f * (gm[0][i][j] * gm[1][i][j] - gm[2][i][j] * gm[2][j][i]);
    red[t] = part;
    __syncthreads();
    if (t == 0) {
        float s = 0.f;
        for (int q = 0; q < 64; q++) s += red[q];
        g_nrm[k] = fmaxf(sqrtf(s), 1e-6f);
    }
}

__global__ void k_P() {
    int idx = blockIdx.x * 256 + threadIdx.x;
    int i = idx >> 7, j = idx & 127;
    float acc = 0.f;
    #pragma unroll 8
    for (int d = 0; d < DD; d++) acc += g_V[d * 128 + i] * g_U[d * 128 + j];
    g_P[idx] = acc;
}

// T0[j][o] = sum_d V[d][j] * W[o][d]; grid (3 o-tiles, 4 j-tiles)
__global__ void __launch_bounds__(256) k_T0(const float* __restrict__ W) {
    int o0 = blockIdx.x * 128, j0 = blockIdx.y * 32;
    __shared__ float As[16][36];    // [k][j]
    __shared__ float Bs[16][132];   // [k][o]
    int tid = threadIdx.x;
    int tx = tid & 31, ty = tid >> 5;
    int ro = tid >> 1, co = tid & 1;
    int ja = tid & 31, ka = tid >> 5;
    float acc[4][4] = {};
    for (int k0 = 0; k0 < DD; k0 += 16) {
        As[ka][ja]     = g_V[(size_t)(k0 + ka) * 128 + j0 + ja];
        As[ka + 8][ja] = g_V[(size_t)(k0 + ka + 8) * 128 + j0 + ja];
        #pragma unroll
        for (int h = 0; h < 2; h++) {
            float4 w = *(const float4*)(W + (size_t)(o0 + ro) * DD + k0 + co * 8 + h * 4);
            Bs[co * 8 + h * 4 + 0][ro] = w.x;
            Bs[co * 8 + h * 4 + 1][ro] = w.y;
            Bs[co * 8 + h * 4 + 2][ro] = w.z;
            Bs[co * 8 + h * 4 + 3][ro] = w.w;
        }
        __syncthreads();
        #pragma unroll
        for (int kk = 0; kk < 16; kk++) {
            float av[4], bv[4];
            #pragma unroll
            for (int i = 0; i < 4; i++) av[i] = As[kk][ty * 4 + i];
            #pragma unroll
            for (int j = 0; j < 4; j++) bv[j] = Bs[kk][tx * 4 + j];
            #pragma unroll
            for (int i = 0; i < 4; i++)
                #pragma unroll
                for (int j = 0; j < 4; j++) acc[i][j] += av[i] * bv[j];
        }
        __syncthreads();
    }
    #pragma unroll
    for (int i = 0; i < 4; i++)
        *(float4*)(g_T0 + (size_t)(j0 + ty * 4 + i) * OUTD + o0 + tx * 4) = *(float4*)acc[i];
}

__global__ void k_ctrl(const float* __restrict__ w1, const float* __restrict__ b1,
                       const float* __restrict__ w_rot, const float* __restrict__ b_rot,
                       const float* __restrict__ w_rg, const float* __restrict__ b_rg,
                       const float* __restrict__ w_lg, const float* __restrict__ b_lg,
                       const float* __restrict__ w_sc, const float* __restrict__ b_sc,
                       const float* __restrict__ scale_basis, const float* __restrict__ ss_ptr) {
    int b = blockIdx.x, t = threadIdx.x;
    int lane = t & 31, wid = t >> 5;
    __shared__ float zs[CIN];
    __shared__ float hs[HH];
    __shared__ float coef[KKB];
    for (int c = t; c < CIN; c += 128) zs[c] = g_z[b * CIN + c];
    __syncthreads();
    for (int to = wid; to < HH; to += 4) {
        const float* w = w1 + (size_t)to * CIN;
        float acc = 0.f;
        for (int c = lane; c < CIN; c += 32) acc += zs[c] * w[c];
        #pragma unroll
        for (int off = 16; off; off >>= 1) acc += __shfl_down_sync(0xFFFFFFFFu, acc, off);
        if (lane == 0) {
            float xg = acc + b1[to];
            float x3 = xg * xg * xg;
            hs[to] = 0.5f * xg * (1.f + tanhf(0.7978845608028654f * (xg + 0.044715f * x3)));
        }
    }
    __syncthreads();
    if (t < 8) {
        float acc = b_rot[t];
        for (int c = 0; c < HH; c++) acc += hs[c] * w_rot[t * HH + c];
        g_s[b * 8 + t] = 0.5f * tanhf(acc) / g_nrm[t];
    } else if (t == 8) {
        float acc = b_rg[0];
        for (int c = 0; c < HH; c++) acc += hs[c] * w_rg[c];
        g_g2[b] = 2.f / (1.f + expf(-acc));
    } else if (t == 9) {
        float acc = b_lg[0];
        for (int c = 0; c < HH; c++) acc += hs[c] * w_lg[c];
        g_lg[b] = 1.f / (1.f + expf(-acc));
    } else if (t >= 16 && t < 24) {
        int k = t - 16;
        float acc = b_sc[k];
        for (int c = 0; c < HH; c++) acc += hs[c] * w_sc[k * HH + c];
        coef[k] = tanhf(acc);
    }
    __syncthreads();
    float ss = ss_ptr[0];
    for (int o = t; o < OUTD; o += 128) {
        float acc = 0.f;
        for (int k = 0; k < KKB; k++) acc += coef[k] * scale_basis[k * OUTD + o];
        g_scale[b * OUTD + o] = 1.f + ss * tanhf(acc);
    }
}

#define LUP 129
#define LUSOLVE_SMEM (2 * 128 * LUP * 4)
__global__ void __launch_bounds__(128) k_lusolve() {
    extern __shared__ float smf[];
    float* a = smf;
    float* y = smf + 128 * LUP;
    __shared__ float sb[8];
    int b = blockIdx.x, i = threadIdx.x;
    if (i < 8) sb[i] = g_s[b * 8 + i];
    __syncthreads();
    for (int q = 0; q < 128; q++)
        a[i * LUP + q] = (i == q ? 1.f : 0.f) - g_P[i * 128 + q] * sb[q >> 4];
    for (int p = 0; p < 127; p++) {
        __syncthreads();
        if (i > p) {
            float l = a[i * LUP + p] / a[p * LUP + p];
            a[i * LUP + p] = l;
            for (int q = p + 1; q < 128; q++) a[i * LUP + q] -= l * a[p * LUP + q];
        }
    }
    __syncthreads();
    for (int p = 0; p < 128; p++) {
        float a0 = 0.f, a1 = 0.f, a2 = 0.f, a3 = 0.f;
        const float* row = a + p * LUP;
        int q = 0;
        for (; q + 3 < p; q += 4) {
            a0 += row[q] * y[q * LUP + i];
            a1 += row[q + 1] * y[(q + 1) * LUP + i];
            a2 += row[q + 2] * y[(q + 2) * LUP + i];
            a3 += row[q + 3] * y[(q + 3) * LUP + i];
        }
        for (; q < p; q++) a0 += row[q] * y[q * LUP + i];
        y[p * LUP + i] = ((p == i) ? 1.f : 0.f) - (a0 + a1) - (a2 + a3);
    }
    for (int p = 127; p >= 0; p--) {
        float a0 = 0.f, a1 = 0.f, a2 = 0.f, a3 = 0.f;
        const float* row = a + p * LUP;
        int q = p + 1;
        for (; q + 3 < 128; q += 4) {
            a0 += row[q] * y[q * LUP + i];
            a1 += row[q + 1] * y[(q + 1) * LUP + i];
            a2 += row[q + 2] * y[(q + 2) * LUP + i];
            a3 += row[q + 3] * y[(q + 3) * LUP + i];
        }
        for (; q < 128; q++) a0 += row[q] * y[q * LUP + i];
        y[p * LUP + i] = (y[p * LUP + i] - (a0 + a1) - (a2 + a3)) / row[p];
    }
    float* sv = g_Sinv + (size_t)b * 128 * 128;
    for (int p = 0; p < 128; p++)
        sv[p * 128 + i] = sb[p >> 4] * y[p * LUP + i];
}

__global__ void __launch_bounds__(256) k_E() {
    int b = blockIdx.z, d0 = blockIdx.y * 128;
    __shared__ __align__(16) float As[16][132];
    __shared__ __align__(16) float Bs[16][132];
    int tid = threadIdx.x, tx = tid & 15, ty = tid >> 4;
    const float* Sv = g_Sinv + (size_t)b * 128 * 128;
    float acc[8][8] = {};
    int ar = tid >> 2, ac = (tid & 3) * 4;
    for (int k0 = 0; k0 < 128; k0 += 16) {
        #pragma unroll
        for (int h = 0; h < 2; h++) {
            int d = d0 + ar + h * 64;
            float4 v = *(const float4*)(g_U + (size_t)d * 128 + k0 + ac);
            As[ac + 0][ar + h * 64] = v.x;
            As[ac + 1][ar + h * 64] = v.y;
            As[ac + 2][ar + h * 64] = v.z;
            As[ac + 3][ar + h * 64] = v.w;
        }
        #pragma unroll
        for (int i2 = 0; i2 < 2; i2++) {
            int idx = tid + i2 * 256;
            int r = idx >> 5, cc = (idx & 31) * 4;
            *(float4*)&Bs[r][cc] = *(const float4*)(Sv + (size_t)(k0 + r) * 128 + cc);
        }
        __syncthreads();
        #pragma unroll
        for (int kk = 0; kk < 16; kk++) {
            float av[8], bv[8];
            *(float4*)&av[0] = *(const float4*)&As[kk][ty * 8];
            *(float4*)&av[4] = *(const float4*)&As[kk][ty * 8 + 4];
            *(float4*)&bv[0] = *(const float4*)&Bs[kk][tx * 8];
            *(float4*)&bv[4] = *(const float4*)&Bs[kk][tx * 8 + 4];
            #pragma unroll
            for (int i = 0; i < 8; i++)
                #pragma unroll
                for (int j = 0; j < 8; j++) acc[i][j] += av[i] * bv[j];
        }
        __syncthreads();
    }
    #pragma unroll
    for (int i = 0; i < 8; i++) {
        float* erow = g_E + ((size_t)b * DD + d0 + ty * 8 + i) * 128 + tx * 8;
        *(float4*)&erow[0] = *(float4*)&acc[i][0];
        *(float4*)&erow[4] = *(float4*)&acc[i][4];
    }
}

__global__ void __launch_bounds__(256) k_weffT(const float* __restrict__ W) {
    int b = blockIdx.z, o0 = blockIdx.y * 128, d0 = blockIdx.x * 128;
    __shared__ __align__(16) float As[16][132];
    __shared__ __align__(16) float Bs[16][132];
    int tid = threadIdx.x, tx = tid & 15, ty = tid >> 4;
    const float* Eb = g_E + (size_t)b * DD * 128;
    float acc[8][8] = {};
    int ar = tid >> 2, ac = (tid & 3) * 4;
    for (int k0 = 0; k0 < 128; k0 += 16) {
        #pragma unroll
        for (int i2 = 0; i2 < 2; i2++) {
            int idx = tid + i2 * 256;
            int r = idx >> 5, cc = (idx & 31) * 4;
            *(float4*)&As[r][cc] = *(const float4*)(g_T0 + (size_t)(k0 + r) * OUTD + o0 + cc);
        }
        #pragma unroll
        for (int h = 0; h < 2; h++) {
            int d = d0 + ar + h * 64;
            float4 v = *(const float4*)(Eb + (size_t)d * 128 + k0 + ac);
            Bs[ac + 0][ar + h * 64] = v.x;
            Bs[ac + 1][ar + h * 64] = v.y;
            Bs[ac + 2][ar + h * 64] = v.z;
            Bs[ac + 3][ar + h * 64] = v.w;
        }
        __syncthreads();
        #pragma unroll
        for (int kk = 0; kk < 16; kk++) {
            float av[8], bv[8];
            *(float4*)&av[0] = *(const float4*)&As[kk][ty * 8];
            *(float4*)&av[4] = *(const float4*)&As[kk][ty * 8 + 4];
            *(float4*)&bv[0] = *(const float4*)&Bs[kk][tx * 8];
            *(float4*)&bv[4] = *(const float4*)&Bs[kk][tx * 8 + 4];
            #pragma unroll
            for (int i = 0; i < 8; i++)
                #pragma unroll
                for (int j = 0; j < 8; j++) acc[i][j] += av[i] * bv[j];
        }
        __syncthreads();
    }
    float g = g_g2[b];
    #pragma unroll
    for (int i = 0; i < 8; i++) {
        int o = o0 + ty * 8 + i;
        const float* wrow = W + (size_t)o * DD + d0 + tx * 8;
        __align__(16) __half hb[8], lb[8];
        #pragma unroll
        for (int j = 0; j < 8; j++) {
            float v = wrow[j] + g * acc[i][j];
            __half h = __float2half(v);
            hb[j] = h;
            lb[j] = __float2half(v - __half2float(h));
        }
        size_t off = ((size_t)b * OUTD + o) * DD + d0 + tx * 8;
        *(uint4*)(g_WTh + off) = *(uint4*)hb;
        *(uint4*)(g_WTl + off) = *(uint4*)lb;
    }
}

__global__ void k_lm(const float* __restrict__ x, const float* __restrict__ ker) {
    int by = blockIdx.x;
    int b = by >> 5, y = by & 31, d = threadIdx.x;
    const float* xb = x + (size_t)b * NN * DD;
    float lg = g_lg[b];
    if (y == 0) g_lmh[(size_t)b * NN * DD + d] = __float2half(xb[d]);
    float k00 = ker[d * 9 + 0], k01 = ker[d * 9 + 1], k02 = ker[d * 9 + 2];
    float k10 = ker[d * 9 + 3], k11 = ker[d * 9 + 4], k12 = ker[d * 9 + 5];
    float k20 = ker[d * 9 + 6], k21 = ker[d * 9 + 7], k22 = ker[d * 9 + 8];
    bool up = (y > 0), dn = (y < 31);
    float ua = 0.f, ma = 0.f, la = 0.f, ub, mb, mc, lb, uc, lc;
    ub = up ? xb[(size_t)(1 + (y - 1) * 32) * DD + d] : 0.f;
    mb = xb[(size_t)(1 + y * 32) * DD + d];
    lb = dn ? xb[(size_t)(1 + (y + 1) * 32) * DD + d] : 0.f;
    for (int xx = 0; xx < 32; xx++) {
        if (xx < 31) {
            uc = up ? xb[(size_t)(1 + (y - 1) * 32 + xx + 1) * DD + d] : 0.f;
            mc = xb[(size_t)(1 + y * 32 + xx + 1) * DD + d];
            lc = dn ? xb[(size_t)(1 + (y + 1) * 32 + xx + 1) * DD + d] : 0.f;
        } else { uc = mc = lc = 0.f; }
        float conv = ua * k00 + ub * k01 + uc * k02 + ma * k10 + mb * k11 + mc * k12
                   + la * k20 + lb * k21 + lc * k22;
        float v = mb + lg * (conv - mb);
        g_lmh[((size_t)b * NN + 1 + y * 32 + xx) * DD + d] = __float2half(v);
        ua = ub; ub = uc; ma = mb; mb = mc; la = lb; lb = lc;
    }
}

// ---------------- main GEMM: fp16, 2 segments (Ah*Bh + Ah*Bl), rows 0..1023 ----------------
#define BK 32
#define ROWB 80
#define TILEB (128 * ROWB)
#define STAGEB (3 * TILEB)
#define NCH 12
#define GEMM_SMEM (2 * STAGEB)

__device__ __forceinline__ void cp16(uint32_t dst, const void* src) {
    asm volatile("cp.async.cg.shared.global [%0], [%1], 16;" :: "r"(dst), "l"(src) : "memory");
}

__global__ void __launch_bounds__(256, 2) k_gemm_mma(const float* __restrict__ bias,
                                                     float* __restrict__ out) {
    extern __shared__ __align__(16) unsigned char sm[];
    __shared__ float s_bias[128], s_scale[128];
    int b = blockIdx.z, m0 = blockIdx.y * 128, n0 = blockIdx.x * 128;
    int tid = threadIdx.x, lane = tid & 31, wid = tid >> 5;
    int wm = wid & 1, wn = wid >> 1;

    if (tid < 128) {
        s_bias[tid] = bias[n0 + tid];
        s_scale[tid] = g_scale[b * OUTD + n0 + tid];
    }

    uint32_t smb = smem_u32(sm);
    float acc[4][4][4];
    #pragma unroll
    for (int i = 0; i < 4; i++)
        #pragma unroll
        for (int j = 0; j < 4; j++)
            #pragma unroll
            for (int q = 0; q < 4; q++) acc[i][j][q] = 0.f;

    int ci0 = tid, ci1 = tid + 256;
    int r0 = ci0 >> 2, ch0 = ci0 & 3;
    int r1 = ci1 >> 2, ch1 = ci1 & 3;
    size_t aoff0 = ((size_t)b * NN + m0 + r0) * DD;
    size_t aoff1 = ((size_t)b * NN + m0 + r1) * DD;
    size_t boff0 = ((size_t)b * OUTD + n0 + r0) * DD;
    size_t boff1 = ((size_t)b * OUTD + n0 + r1) * DD;

    #define LOAD_CHUNK(c, s) do { \
        int k0 = (c) * BK; \
        uint32_t Ah = smb + (uint32_t)(s) * STAGEB; \
        uint32_t Bh = Ah + TILEB, Bl = Ah + 2 * TILEB; \
        cp16(Ah + r0 * ROWB + ch0 * 16, g_lmh + aoff0 + k0 + ch0 * 8); \
        cp16(Ah + r1 * ROWB + ch1 * 16, g_lmh + aoff1 + k0 + ch1 * 8); \
        cp16(Bh + r0 * ROWB + ch0 * 16, g_WTh + boff0 + k0 + ch0 * 8); \
        cp16(Bh + r1 * ROWB + ch1 * 16, g_WTh + boff1 + k0 + ch1 * 8); \
        cp16(Bl + r0 * ROWB + ch0 * 16, g_WTl + boff0 + k0 + ch0 * 8); \
        cp16(Bl + r1 * ROWB + ch1 * 16, g_WTl + boff1 + k0 + ch1 * 8); \
    } while (0)

    #define LDMA(dst, base, mf) do { \
        uint32_t addr = (base) + (uint32_t)((wm * 64 + (mf) * 16 + (lane & 15)) * ROWB \
                      + (kstep * 2 + (lane >> 4)) * 16); \
        asm volatile("ldmatrix.sync.aligned.m8n8.x4.shared.b16 {%0,%1,%2,%3}, [%4];" \
            : "=r"((dst)[0]), "=r"((dst)[1]), "=r"((dst)[2]), "=r"((dst)[3]) : "r"(addr)); \
    } while (0)

    #define LDMB(dst, base) do { \
        int g = lane >> 3; \
        _Pragma("unroll") \
        for (int nf2 = 0; nf2 < 2; nf2++) { \
            uint32_t addr = (base) + (uint32_t)((wn * 32 + nf2 * 16 + ((g >> 1) << 3) + (lane & 7)) * ROWB \
                          + (kstep * 2 + (g & 1)) * 16); \
            uint32_t q0, q1, q2, q3; \
            asm volatile("ldmatrix.sync.aligned.m8n8.x4.shared.b16 {%0,%1,%2,%3}, [%4];" \
                : "=r"(q0), "=r"(q1), "=r"(q2), "=r"(q3) : "r"(addr)); \
            (dst)[nf2 * 2][0] = q0; (dst)[nf2 * 2][1] = q1; \
            (dst)[nf2 * 2 + 1][0] = q2; (dst)[nf2 * 2 + 1][1] = q3; \
        } \
    } while (0)

    #define MMAS(af, bfr) do { \
        _Pragma("unroll") \
        for (int mf = 0; mf < 4; mf++) \
            _Pragma("unroll") \
            for (int nf = 0; nf < 4; nf++) { \
                asm volatile( \
                    "mma.sync.aligned.m16n8k16.row.col.f32.f16.f16.f32 " \
                    "{%0,%1,%2,%3}, {%4,%5,%6,%7}, {%8,%9}, {%0,%1,%2,%3};" \
                    : "+f"(acc[mf][nf][0]), "+f"(acc[mf][nf][1]), \
                      "+f"(acc[mf][nf][2]), "+f"(acc[mf][nf][3]) \
                    : "r"((af)[mf][0]), "r"((af)[mf][1]), "r"((af)[mf][2]), "r"((af)[mf][3]), \
                      "r"((bfr)[nf][0]), "r"((bfr)[nf][1])); \
            } \
    } while (0)

    LOAD_CHUNK(0, 0);
    asm volatile("cp.async.commit_group;" ::: "memory");

    for (int c = 0; c < NCH; c++) {
        if (c + 1 < NCH) {
            LOAD_CHUNK(c + 1, (c + 1) & 1);
            asm volatile("cp.async.commit_group;" ::: "memory");
            asm volatile("cp.async.wait_group 1;" ::: "memory");
        } else {
            asm volatile("cp.async.wait_group 0;" ::: "memory");
        }
        __syncthreads();

        uint32_t Ah = smb + (uint32_t)(c & 1) * STAGEB;
        uint32_t Bh = Ah + TILEB, Bl = Ah + 2 * TILEB;
        #pragma unroll
        for (int kstep = 0; kstep < 2; kstep++) {
            uint32_t ah[4][4], bh[4][2], bl[4][2];
            #pragma unroll
            for (int mf = 0; mf < 4; mf++) LDMA(ah[mf], Ah, mf);
            LDMB(bh, Bh);
            MMAS(ah, bh);
            LDMB(bl, Bl);
            MMAS(ah, bl);
        }
        __syncthreads();
    }

    int gr = lane >> 2, gc = (lane & 3) * 2;
    #pragma unroll
    for (int mf = 0; mf < 4; mf++) {
        #pragma unroll
        for (int nf = 0; nf < 4; nf++) {
            int nl = wn * 32 + nf * 8 + gc;
            float b0 = s_bias[nl], b1 = s_bias[nl + 1];
            float sc0 = s_scale[nl], sc1 = s_scale[nl + 1];
            int mrow = m0 + wm * 64 + mf * 16 + gr;
            float2 v0 = make_float2((acc[mf][nf][0] + b0) * sc0, (acc[mf][nf][1] + b1) * sc1);
            *(float2*)(out + ((size_t)b * NN + mrow) * OUTD + n0 + nl) = v0;
            float2 v1 = make_float2((acc[mf][nf][2] + b0) * sc0, (acc[mf][nf][3] + b1) * sc1);
            *(float2*)(out + ((size_t)b * NN + mrow + 8) * OUTD + n0 + nl) = v1;
        }
    }
}

__global__ void k_lastrow(const float* __restrict__ bias, float* __restrict__ out) {
    int b = blockIdx.x, o = threadIdx.x;
    __shared__ float av[DD];
    size_t lro = ((size_t)b * NN + NN - 1) * DD;
    for (int d = o; d < DD; d += 384)
        av[d] = __half2float(g_lmh[lro + d]);
    __syncthreads();
    const __half2* wh = (const __half2*)(g_WTh + ((size_t)b * OUTD + o) * DD);
    const __half2* wl = (const __half2*)(g_WTl + ((size_t)b * OUTD + o) * DD);
    float acc = 0.f;
    #pragma unroll 4
    for (int d2 = 0; d2 < DD / 2; d2++) {
        float2 h = __half22float2(wh[d2]);
        float2 l = __half22float2(wl[d2]);
        acc += av[d2 * 2] * (h.x + l.x) + av[d2 * 2 + 1] * (h.y + l.y);
    }
    out[lro / DD * OUTD + o] = (acc + bias[o]) * g_scale[b * OUTD + o];
}

// ---------------- launch with fork-join stream overlap ----------------
static cudaStream_t s1, s2;
static cudaEvent_t ev_fork, ev_norms, ev_P, ev_T0, ev_ctrl, ev_lm;

extern "C" void kernel_launch(void* const* d_in, const int* in_sizes, int n_in,
                              void* d_out, int out_size) {
    const float* x      = (const float*)d_in[0];
    const float* W      = (const float*)d_in[1];
    const float* bias   = (const float*)d_in[2];
    const float* Lb     = (const float*)d_in[3];
    const float* Rb     = (const float*)d_in[4];
    const float* sbasis = (const float*)d_in[5];
    const float* ss     = (const float*)d_in[6];
    const float* dwk    = (const float*)d_in[7];
    const float* w1     = (const float*)d_in[8];
    const float* b1     = (const float*)d_in[9];
    const float* w_rot  = (const float*)d_in[10];
    const float* b_rot  = (const float*)d_in[11];
    const float* w_rg   = (const float*)d_in[12];
    const float* b_rg   = (const float*)d_in[13];
    const float* w_lg   = (const float*)d_in[14];
    const float* b_lg   = (const float*)d_in[15];
    const float* w_sc   = (const float*)d_in[16];
    const float* b_sc   = (const float*)d_in[17];
    float* out = (float*)d_out;

    static int init_done = 0;
    if (!init_done) {
        cudaFuncSetAttribute(k_lusolve, cudaFuncAttributeMaxDynamicSharedMemorySize, LUSOLVE_SMEM);
        cudaFuncSetAttribute(k_gemm_mma, cudaFuncAttributeMaxDynamicSharedMemorySize, GEMM_SMEM);
        cudaStreamCreateWithFlags(&s1, cudaStreamNonBlocking);
        cudaStreamCreateWithFlags(&s2, cudaStreamNonBlocking);
        cudaEventCreateWithFlags(&ev_fork, cudaEventDisableTiming);
        cudaEventCreateWithFlags(&ev_norms, cudaEventDisableTiming);
        cudaEventCreateWithFlags(&ev_P, cudaEventDisableTiming);
        cudaEventCreateWithFlags(&ev_T0, cudaEventDisableTiming);
        cudaEventCreateWithFlags(&ev_ctrl, cudaEventDisableTiming);
        cudaEventCreateWithFlags(&ev_lm, cudaEventDisableTiming);
        init_done = 1;
    }

    cudaEventRecord(ev_fork, 0);
    cudaStreamWaitEvent(s1, ev_fork, 0);

    // s1: basis chain; T0 deliberately AFTER ev_P so lusolve can start early
    k_build_uv<<<(DD * 128) / 256, 256, 0, s1>>>(Lb, Rb);
    k_norms<<<KKB, 192, 0, s1>>>(Lb, Rb);
    cudaEventRecord(ev_norms, s1);
    k_P<<<(128 * 128) / 256, 256, 0, s1>>>();
    cudaEventRecord(ev_P, s1);
    k_T0<<<dim3(3, 4), 256, 0, s1>>>(W);
    cudaEventRecord(ev_T0, s1);

    // origin: stats -> ctrl (needs norms)
    k_stats<<<(BB * DD) / 128, 128>>>(x);
    cudaStreamWaitEvent(0, ev_norms, 0);
    k_ctrl<<<BB, 128>>>(w1, b1, w_rot, b_rot, w_rg, b_rg, w_lg, b_lg, w_sc, b_sc, sbasis, ss);
    cudaEventRecord(ev_ctrl, 0);

    // s2: lm (needs ctrl's local_gate), overlaps the solve chain
    cudaStreamWaitEvent(s2, ev_ctrl, 0);
    k_lm<<<BB * 32, 384, 0, s2>>>(x, dwk);
    cudaEventRecord(ev_lm, s2);

    // origin: lusolve (needs P) -> E -> weffT (needs T0)
    cudaStreamWaitEvent(0, ev_P, 0);
    k_lusolve<<<BB, 128, LUSOLVE_SMEM>>>();
    k_E<<<dim3(1, 3, BB), 256>>>();
    cudaStreamWaitEvent(0, ev_T0, 0);
    k_weffT<<<dim3(3, 3, BB), 256>>>(W);

    cudaStreamWaitEvent(0, ev_lm, 0);
    k_gemm_mma<<<dim3(3, 8, BB), 256, GEMM_SMEM>>>(bias, out);
    k_lastrow<<<BB, 384>>>(bias, out);
}